// round 2
// baseline (speedup 1.0000x reference)
#include <cuda_runtime.h>
#include <cstdint>

#define N_NODES 50000
#define EMBED_DIM 512
#define N_EDGES 800000
#define NEG_SLOPE 0.01f

// -------- scratch (allocation-free: __device__ globals) --------
__device__ float g_Hs[(size_t)N_NODES * EMBED_DIM];  // H * dinv[row]
__device__ int   g_deg[N_NODES];
__device__ float g_dinv[N_NODES];

// -------------------- degree / norm --------------------
__global__ void init_deg_kernel() {
    int i = blockIdx.x * blockDim.x + threadIdx.x;
    if (i < N_NODES) g_deg[i] = 1;  // self-loop
}

__global__ void count_deg_kernel(const int* __restrict__ dst) {
    int e = blockIdx.x * blockDim.x + threadIdx.x;
    if (e < N_EDGES) atomicAdd(&g_deg[dst[e]], 1);
}

__global__ void dinv_kernel() {
    int i = blockIdx.x * blockDim.x + threadIdx.x;
    if (i < N_NODES) g_dinv[i] = rsqrtf((float)g_deg[i]);
}

// -------------------- GEMM: Hs = (X @ W) * dinv[row]; out init = Hs --------------------
// BM=128, BN=128, BK=16, 256 threads, 8x8 per thread.
__global__ __launch_bounds__(256) void gemm_kernel(
    const float* __restrict__ X, const float* __restrict__ W,
    float* __restrict__ out)
{
    __shared__ float As[16][128];   // transposed: As[k][m]
    __shared__ float Bs[16][128];   // Bs[k][n]

    const int tid = threadIdx.x;
    const int tx = tid & 15;        // col group
    const int ty = tid >> 4;        // row group
    const int rowBase = blockIdx.x * 128;
    const int colBase = blockIdx.y * 128;

    float acc[8][8];
    #pragma unroll
    for (int i = 0; i < 8; i++)
        #pragma unroll
        for (int j = 0; j < 8; j++) acc[i][j] = 0.f;

    for (int k0 = 0; k0 < EMBED_DIM; k0 += 16) {
        // load A tile: 128 rows x 16 k  (512 float4 slots, 2 per thread)
        #pragma unroll
        for (int s = 0; s < 2; s++) {
            int slot = tid + s * 256;
            int a_row = slot >> 2;
            int a_vec = slot & 3;
            int gRow = rowBase + a_row;
            float4 v = make_float4(0.f, 0.f, 0.f, 0.f);
            if (gRow < N_NODES)
                v = *reinterpret_cast<const float4*>(&X[(size_t)gRow * EMBED_DIM + k0 + a_vec * 4]);
            As[a_vec * 4 + 0][a_row] = v.x;
            As[a_vec * 4 + 1][a_row] = v.y;
            As[a_vec * 4 + 2][a_row] = v.z;
            As[a_vec * 4 + 3][a_row] = v.w;
        }
        // load B tile: 16 k x 128 cols (512 float4 slots, 2 per thread)
        #pragma unroll
        for (int s = 0; s < 2; s++) {
            int slot = tid + s * 256;
            int b_row = slot >> 5;          // 0..15
            int b_vec = slot & 31;          // 0..31
            float4 v = *reinterpret_cast<const float4*>(
                &W[(size_t)(k0 + b_row) * EMBED_DIM + colBase + b_vec * 4]);
            *reinterpret_cast<float4*>(&Bs[b_row][b_vec * 4]) = v;
        }
        __syncthreads();

        #pragma unroll
        for (int k = 0; k < 16; k++) {
            float a_frag[8], b_frag[8];
            *reinterpret_cast<float4*>(&a_frag[0]) = *reinterpret_cast<const float4*>(&As[k][ty * 8]);
            *reinterpret_cast<float4*>(&a_frag[4]) = *reinterpret_cast<const float4*>(&As[k][ty * 8 + 4]);
            *reinterpret_cast<float4*>(&b_frag[0]) = *reinterpret_cast<const float4*>(&Bs[k][tx * 8]);
            *reinterpret_cast<float4*>(&b_frag[4]) = *reinterpret_cast<const float4*>(&Bs[k][tx * 8 + 4]);
            #pragma unroll
            for (int i = 0; i < 8; i++)
                #pragma unroll
                for (int j = 0; j < 8; j++)
                    acc[i][j] = fmaf(a_frag[i], b_frag[j], acc[i][j]);
        }
        __syncthreads();
    }

    // epilogue: scale by dinv[row], write Hs and out (self-loop init)
    #pragma unroll
    for (int i = 0; i < 8; i++) {
        int gRow = rowBase + ty * 8 + i;
        if (gRow >= N_NODES) continue;
        float s = g_dinv[gRow];
        size_t base = (size_t)gRow * EMBED_DIM + colBase + tx * 8;
        #pragma unroll
        for (int j = 0; j < 8; j += 4) {
            float4 v;
            v.x = acc[i][j + 0] * s;
            v.y = acc[i][j + 1] * s;
            v.z = acc[i][j + 2] * s;
            v.w = acc[i][j + 3] * s;
            *reinterpret_cast<float4*>(&g_Hs[base + j]) = v;
            *reinterpret_cast<float4*>(&out[base + j]) = v;
        }
    }
}

// -------------------- scatter: out[dst] += Hs[src]  (vector red) --------------------
__device__ __forceinline__ void red_add_v4(float* addr, float4 v) {
    asm volatile("red.global.add.v4.f32 [%0], {%1, %2, %3, %4};"
                 :: "l"(addr), "f"(v.x), "f"(v.y), "f"(v.z), "f"(v.w)
                 : "memory");
}

__global__ __launch_bounds__(256) void scatter_kernel(
    const int* __restrict__ src, const int* __restrict__ dst,
    float* __restrict__ out)
{
    int warp = (blockIdx.x * blockDim.x + threadIdx.x) >> 5;
    if (warp >= N_EDGES) return;
    int lane = threadIdx.x & 31;
    int s = __ldg(&src[warp]);
    int d = __ldg(&dst[warp]);
    const float4* hrow = reinterpret_cast<const float4*>(&g_Hs[(size_t)s * EMBED_DIM]);
    float* orow = &((float*)nullptr)[0];  // placate compiler; real ptr below
    float* obase = out + (size_t)d * EMBED_DIM;
    (void)orow;
    #pragma unroll
    for (int i = lane; i < EMBED_DIM / 4; i += 32) {
        float4 v = __ldg(&hrow[i]);
        red_add_v4(obase + i * 4, v);
    }
}

// -------------------- finalize: out = leaky(out * dinv[row] + b) --------------------
__global__ __launch_bounds__(256) void finalize_kernel(
    float* __restrict__ out, const float* __restrict__ b)
{
    size_t idx = (size_t)blockIdx.x * blockDim.x + threadIdx.x;  // float4 index
    const size_t total = (size_t)N_NODES * EMBED_DIM / 4;
    if (idx >= total) return;
    int row = (int)(idx / (EMBED_DIM / 4));
    int cv = (int)(idx % (EMBED_DIM / 4));
    float s = g_dinv[row];
    float4 v = reinterpret_cast<float4*>(out)[idx];
    float4 bb = reinterpret_cast<const float4*>(b)[cv];
    float t;
    t = v.x * s + bb.x; v.x = (t >= 0.f) ? t : NEG_SLOPE * t;
    t = v.y * s + bb.y; v.y = (t >= 0.f) ? t : NEG_SLOPE * t;
    t = v.z * s + bb.z; v.z = (t >= 0.f) ? t : NEG_SLOPE * t;
    t = v.w * s + bb.w; v.w = (t >= 0.f) ? t : NEG_SLOPE * t;
    reinterpret_cast<float4*>(out)[idx] = v;
}

// -------------------- launch --------------------
extern "C" void kernel_launch(void* const* d_in, const int* in_sizes, int n_in,
                              void* d_out, int out_size) {
    const float* X = (const float*)d_in[0];
    const float* W = (const float*)d_in[1];
    const float* b = (const float*)d_in[2];
    const int* edge = (const int*)d_in[3];
    const int* src = edge;
    const int* dst = edge + N_EDGES;
    float* out = (float*)d_out;

    init_deg_kernel<<<(N_NODES + 255) / 256, 256>>>();
    count_deg_kernel<<<(N_EDGES + 255) / 256, 256>>>(dst);
    dinv_kernel<<<(N_NODES + 255) / 256, 256>>>();

    dim3 ggrid((N_NODES + 127) / 128, EMBED_DIM / 128);
    gemm_kernel<<<ggrid, 256>>>(X, W, out);

    // one warp per edge, 8 warps per block
    scatter_kernel<<<(N_EDGES + 7) / 8, 256>>>(src, dst, out);

    size_t total4 = (size_t)N_NODES * EMBED_DIM / 4;
    finalize_kernel<<<(unsigned)((total4 + 255) / 256), 256>>>(out, b);
}

// round 5
// speedup vs baseline: 2.3629x; 2.3629x over previous
#include <cuda_runtime.h>
#include <cstdint>

#define N_NODES 50000
#define EMBED_DIM 512
#define N_EDGES 800000
#define NEG_SLOPE 0.01f

// -------- scratch (allocation-free: __device__ globals) --------
__device__ float g_Hs[(size_t)N_NODES * EMBED_DIM];  // (X@W) * dinv[row]
__device__ int   g_deg[N_NODES];
__device__ float g_dinv[N_NODES];

// -------------------- degree / norm --------------------
__global__ void init_deg_kernel() {
    int i = blockIdx.x * blockDim.x + threadIdx.x;
    if (i < N_NODES) g_deg[i] = 1;  // self-loop
}
__global__ void count_deg_kernel(const int* __restrict__ dst) {
    int e = blockIdx.x * blockDim.x + threadIdx.x;
    if (e < N_EDGES) atomicAdd(&g_deg[dst[e]], 1);
}
__global__ void dinv_kernel() {
    int i = blockIdx.x * blockDim.x + threadIdx.x;
    if (i < N_NODES) g_dinv[i] = rsqrtf((float)g_deg[i]);
}

// ==================== mma.sync TF32 GEMM ====================
// Hs = (X @ W) * dinv[row]; out initialized to Hs (self-loop term).
// BM=128, BN=128, BK=32. 256 threads = 8 warps in 2(M) x 4(N).
// Warp tile 64x32 = 4x4 tiles of m16n8k8. cp.async double buffer.

#define BM 128
#define BN 128
#define BK 32
#define A_ROW_STRIDE 144   // 32 floats (128B) + 16B pad
#define B_ROW_STRIDE 544   // 128 floats (512B) + 32B pad
#define A_TILE_BYTES (BM * A_ROW_STRIDE)          // 18432
#define B_TILE_BYTES (BK * B_ROW_STRIDE)          // 17408
#define STAGE_BYTES (A_TILE_BYTES + B_TILE_BYTES) // 35840
#define SMEM_TOTAL (2 * STAGE_BYTES)              // 71680

__device__ __forceinline__ uint32_t smem_u32(const void* p) {
    uint32_t a;
    asm("{ .reg .u64 t; cvta.to.shared.u64 t, %1; cvt.u32.u64 %0, t; }" : "=r"(a) : "l"(p));
    return a;
}
__device__ __forceinline__ void cp_async16(uint32_t dst, const float* src, int sz) {
    asm volatile("cp.async.cg.shared.global [%0], [%1], 16, %2;"
                 :: "r"(dst), "l"(src), "r"(sz));
}
__device__ __forceinline__ uint32_t f2tf32(float v) {
    uint32_t u;
    asm("cvt.rna.tf32.f32 %0, %1;" : "=r"(u) : "f"(v));
    return u;
}
__device__ __forceinline__ void mma_tf32(float& d0, float& d1, float& d2, float& d3,
                                         uint32_t a0, uint32_t a1, uint32_t a2, uint32_t a3,
                                         uint32_t b0, uint32_t b1) {
    asm volatile(
        "mma.sync.aligned.m16n8k8.row.col.f32.tf32.tf32.f32 "
        "{%0,%1,%2,%3}, {%4,%5,%6,%7}, {%8,%9}, {%0,%1,%2,%3};"
        : "+f"(d0), "+f"(d1), "+f"(d2), "+f"(d3)
        : "r"(a0), "r"(a1), "r"(a2), "r"(a3), "r"(b0), "r"(b1));
}

__device__ __forceinline__ void load_chunk(const float* __restrict__ X,
                                           const float* __restrict__ W,
                                           int rowBase, int colBase, int k0,
                                           uint32_t sA, uint32_t sB, int tid) {
    // A: 128 rows x 32 floats = 1024 16B chunks (4/thread)
    #pragma unroll
    for (int s = 0; s < 4; s++) {
        int q = tid + s * 256;
        int r = q >> 3, ch = q & 7;
        int gRow = rowBase + r;
        int ok = (gRow < N_NODES);
        const float* src = X + (size_t)(ok ? gRow : 0) * EMBED_DIM + k0 + ch * 4;
        cp_async16(sA + r * A_ROW_STRIDE + ch * 16, src, ok ? 16 : 0);
    }
    // B: 32 k-rows x 128 floats = 1024 16B chunks (4/thread)
    #pragma unroll
    for (int s = 0; s < 4; s++) {
        int q = tid + s * 256;
        int kr = q >> 5, ch = q & 31;
        const float* src = W + (size_t)(k0 + kr) * EMBED_DIM + colBase + ch * 4;
        cp_async16(sB + kr * B_ROW_STRIDE + ch * 16, src, 16);
    }
}

__global__ __launch_bounds__(256, 1) void gemm_mma_kernel(
    const float* __restrict__ X, const float* __restrict__ W,
    float* __restrict__ out)
{
    extern __shared__ char smem[];
    const uint32_t sbase = smem_u32(smem);
    const int tid = threadIdx.x;
    const int rowBase = blockIdx.x * BM;
    const int colBase = blockIdx.y * BN;

    const int w = tid >> 5, lane = tid & 31;
    const int warpM = w & 1, warpN = w >> 1;   // 2 x 4
    const int g = lane >> 2, c4 = lane & 3;

    float acc[4][4][4];
    #pragma unroll
    for (int i = 0; i < 4; i++)
        #pragma unroll
        for (int j = 0; j < 4; j++)
            #pragma unroll
            for (int r = 0; r < 4; r++) acc[i][j][r] = 0.f;

    // prologue: chunks 0, 1
    load_chunk(X, W, rowBase, colBase, 0, sbase, sbase + A_TILE_BYTES, tid);
    asm volatile("cp.async.commit_group;" ::: "memory");
    load_chunk(X, W, rowBase, colBase, BK,
               sbase + STAGE_BYTES, sbase + STAGE_BYTES + A_TILE_BYTES, tid);
    asm volatile("cp.async.commit_group;" ::: "memory");

    const int NCHUNKS = EMBED_DIM / BK;  // 16
    for (int cidx = 0; cidx < NCHUNKS; cidx++) {
        const int buf = cidx & 1;
        asm volatile("cp.async.wait_group 1;" ::: "memory");
        __syncthreads();

        const char* As = smem + buf * STAGE_BYTES;
        const char* Bs = As + A_TILE_BYTES;
        const int aRow0 = warpM * 64 + g;          // + i*16 (+8)
        const int bCol0 = warpN * 32 + g;          // + j*8

        #pragma unroll
        for (int ks = 0; ks < 4; ks++) {
            const int k0 = ks * 8;
            uint32_t af[4][4], bf[4][2];
            #pragma unroll
            for (int i = 0; i < 4; i++) {
                const char* base = As + (aRow0 + i * 16) * A_ROW_STRIDE + (k0 + c4) * 4;
                af[i][0] = f2tf32(*(const float*)(base));
                af[i][1] = f2tf32(*(const float*)(base + 8 * A_ROW_STRIDE));
                af[i][2] = f2tf32(*(const float*)(base + 16));
                af[i][3] = f2tf32(*(const float*)(base + 8 * A_ROW_STRIDE + 16));
            }
            #pragma unroll
            for (int j = 0; j < 4; j++) {
                const char* base = Bs + (k0 + c4) * B_ROW_STRIDE + (bCol0 + j * 8) * 4;
                bf[j][0] = f2tf32(*(const float*)(base));
                bf[j][1] = f2tf32(*(const float*)(base + 4 * B_ROW_STRIDE));
            }
            #pragma unroll
            for (int i = 0; i < 4; i++)
                #pragma unroll
                for (int j = 0; j < 4; j++)
                    mma_tf32(acc[i][j][0], acc[i][j][1], acc[i][j][2], acc[i][j][3],
                             af[i][0], af[i][1], af[i][2], af[i][3],
                             bf[j][0], bf[j][1]);
        }

        __syncthreads();
        if (cidx + 2 < NCHUNKS) {
            load_chunk(X, W, rowBase, colBase, (cidx + 2) * BK,
                       sbase + buf * STAGE_BYTES,
                       sbase + buf * STAGE_BYTES + A_TILE_BYTES, tid);
        }
        asm volatile("cp.async.commit_group;" ::: "memory");
    }

    // epilogue: scale by dinv[row], write Hs and out (self-loop init)
    #pragma unroll
    for (int i = 0; i < 4; i++) {
        #pragma unroll
        for (int half = 0; half < 2; half++) {
            int row = rowBase + warpM * 64 + i * 16 + g + half * 8;
            if (row >= N_NODES) continue;
            float s = g_dinv[row];
            size_t base = (size_t)row * EMBED_DIM + colBase + warpN * 32 + 2 * c4;
            #pragma unroll
            for (int j = 0; j < 4; j++) {
                float2 v;
                v.x = acc[i][j][half * 2 + 0] * s;
                v.y = acc[i][j][half * 2 + 1] * s;
                *reinterpret_cast<float2*>(&g_Hs[base + j * 8]) = v;
                *reinterpret_cast<float2*>(&out[base + j * 8]) = v;
            }
        }
    }
}

// -------------------- scatter: out[dst] += Hs[src]  (vector red) --------------------
__device__ __forceinline__ void red_add_v4(float* addr, float4 v) {
    asm volatile("red.global.add.v4.f32 [%0], {%1, %2, %3, %4};"
                 :: "l"(addr), "f"(v.x), "f"(v.y), "f"(v.z), "f"(v.w)
                 : "memory");
}

__global__ __launch_bounds__(256) void scatter_kernel(
    const int* __restrict__ src, const int* __restrict__ dst,
    float* __restrict__ out)
{
    int warp = (blockIdx.x * blockDim.x + threadIdx.x) >> 5;
    if (warp >= N_EDGES) return;
    int lane = threadIdx.x & 31;
    int s = __ldg(&src[warp]);
    int d = __ldg(&dst[warp]);
    const float4* hrow = reinterpret_cast<const float4*>(&g_Hs[(size_t)s * EMBED_DIM]);
    float* obase = out + (size_t)d * EMBED_DIM;
    #pragma unroll
    for (int i = lane; i < EMBED_DIM / 4; i += 32) {
        float4 v = __ldg(&hrow[i]);
        red_add_v4(obase + i * 4, v);
    }
}

// -------------------- finalize: out = leaky(out * dinv[row] + b) --------------------
__global__ __launch_bounds__(256) void finalize_kernel(
    float* __restrict__ out, const float* __restrict__ b)
{
    size_t idx = (size_t)blockIdx.x * blockDim.x + threadIdx.x;  // float4 index
    const size_t total = (size_t)N_NODES * EMBED_DIM / 4;
    if (idx >= total) return;
    int row = (int)(idx / (EMBED_DIM / 4));
    int cv = (int)(idx % (EMBED_DIM / 4));
    float s = g_dinv[row];
    float4 v = reinterpret_cast<float4*>(out)[idx];
    float4 bb = reinterpret_cast<const float4*>(b)[cv];
    float t;
    t = v.x * s + bb.x; v.x = (t >= 0.f) ? t : NEG_SLOPE * t;
    t = v.y * s + bb.y; v.y = (t >= 0.f) ? t : NEG_SLOPE * t;
    t = v.z * s + bb.z; v.z = (t >= 0.f) ? t : NEG_SLOPE * t;
    t = v.w * s + bb.w; v.w = (t >= 0.f) ? t : NEG_SLOPE * t;
    reinterpret_cast<float4*>(out)[idx] = v;
}

// -------------------- launch --------------------
extern "C" void kernel_launch(void* const* d_in, const int* in_sizes, int n_in,
                              void* d_out, int out_size) {
    const float* X = (const float*)d_in[0];
    const float* W = (const float*)d_in[1];
    const float* b = (const float*)d_in[2];
    const int* edge = (const int*)d_in[3];
    const int* src = edge;
    const int* dst = edge + N_EDGES;
    float* out = (float*)d_out;

    init_deg_kernel<<<(N_NODES + 255) / 256, 256>>>();
    count_deg_kernel<<<(N_EDGES + 255) / 256, 256>>>(dst);
    dinv_kernel<<<(N_NODES + 255) / 256, 256>>>();

    cudaFuncSetAttribute(gemm_mma_kernel,
                         cudaFuncAttributeMaxDynamicSharedMemorySize, SMEM_TOTAL);
    dim3 ggrid((N_NODES + BM - 1) / BM, EMBED_DIM / BN);
    gemm_mma_kernel<<<ggrid, 256, SMEM_TOTAL>>>(X, W, out);

    scatter_kernel<<<(N_EDGES + 7) / 8, 256>>>(src, dst, out);

    size_t total4 = (size_t)N_NODES * EMBED_DIM / 4;
    finalize_kernel<<<(unsigned)((total4 + 255) / 256), 256>>>(out, b);
}

// round 7
// speedup vs baseline: 3.5293x; 1.4936x over previous
#include <cuda_runtime.h>
#include <cstdint>

#define N_NODES 50000
#define EMBED_DIM 512
#define N_EDGES 800000
#define NEG_SLOPE 0.01f

// -------- scratch (allocation-free: __device__ globals) --------
__device__ float g_Hs[(size_t)N_NODES * EMBED_DIM];  // (X@W) * dinv[row]
__device__ int   g_deg[N_NODES];                     // 1 + in-degree
__device__ float g_dinv[N_NODES];
__device__ int   g_row_start[N_NODES + 1];
__device__ int   g_cursor[N_NODES];
__device__ int   g_csr_src[N_EDGES];

// -------------------- degree / norm --------------------
__global__ void init_deg_kernel() {
    int i = blockIdx.x * blockDim.x + threadIdx.x;
    if (i < N_NODES) g_deg[i] = 1;  // self-loop
}
__global__ void count_deg_kernel(const int* __restrict__ dst) {
    int e = blockIdx.x * blockDim.x + threadIdx.x;
    if (e < N_EDGES) atomicAdd(&g_deg[dst[e]], 1);
}
__global__ void dinv_kernel() {
    int i = blockIdx.x * blockDim.x + threadIdx.x;
    if (i < N_NODES) g_dinv[i] = rsqrtf((float)g_deg[i]);
}

// -------------------- CSR build: exclusive scan of (deg-1), then fill --------------------
__global__ __launch_bounds__(1024) void scan_kernel() {
    __shared__ int sums[1024];
    const int CHUNK = (N_NODES + 1023) / 1024;  // 49
    int t = threadIdx.x;
    int begin = t * CHUNK;
    int end = begin + CHUNK; if (end > N_NODES) end = N_NODES;
    int s = 0;
    for (int i = begin; i < end; i++) s += g_deg[i] - 1;
    sums[t] = s;
    __syncthreads();
    // inclusive Hillis-Steele scan
    #pragma unroll
    for (int off = 1; off < 1024; off <<= 1) {
        int v = (t >= off) ? sums[t - off] : 0;
        __syncthreads();
        sums[t] += v;
        __syncthreads();
    }
    int run = (t == 0) ? 0 : sums[t - 1];
    for (int i = begin; i < end; i++) {
        g_row_start[i] = run;
        g_cursor[i] = run;
        run += g_deg[i] - 1;
    }
    if (t == 1023) g_row_start[N_NODES] = run;  // == N_EDGES
}

__global__ void csr_fill_kernel(const int* __restrict__ src, const int* __restrict__ dst) {
    int e = blockIdx.x * blockDim.x + threadIdx.x;
    if (e >= N_EDGES) return;
    int d = dst[e];
    int pos = atomicAdd(&g_cursor[d], 1);
    g_csr_src[pos] = src[e];
}

// ==================== mma.sync TF32 GEMM ====================
// Hs = (X @ W) * dinv[row].
#define BM 128
#define BN 128
#define BK 32
#define A_ROW_STRIDE 144
#define B_ROW_STRIDE 544
#define A_TILE_BYTES (BM * A_ROW_STRIDE)
#define B_TILE_BYTES (BK * B_ROW_STRIDE)
#define STAGE_BYTES (A_TILE_BYTES + B_TILE_BYTES)
#define SMEM_TOTAL (2 * STAGE_BYTES)

__device__ __forceinline__ uint32_t smem_u32(const void* p) {
    uint32_t a;
    asm("{ .reg .u64 t; cvta.to.shared.u64 t, %1; cvt.u32.u64 %0, t; }" : "=r"(a) : "l"(p));
    return a;
}
__device__ __forceinline__ void cp_async16(uint32_t dst, const float* src, int sz) {
    asm volatile("cp.async.cg.shared.global [%0], [%1], 16, %2;"
                 :: "r"(dst), "l"(src), "r"(sz));
}
__device__ __forceinline__ uint32_t f2tf32(float v) {
    uint32_t u;
    asm("cvt.rna.tf32.f32 %0, %1;" : "=r"(u) : "f"(v));
    return u;
}
__device__ __forceinline__ void mma_tf32(float& d0, float& d1, float& d2, float& d3,
                                         uint32_t a0, uint32_t a1, uint32_t a2, uint32_t a3,
                                         uint32_t b0, uint32_t b1) {
    asm volatile(
        "mma.sync.aligned.m16n8k8.row.col.f32.tf32.tf32.f32 "
        "{%0,%1,%2,%3}, {%4,%5,%6,%7}, {%8,%9}, {%0,%1,%2,%3};"
        : "+f"(d0), "+f"(d1), "+f"(d2), "+f"(d3)
        : "r"(a0), "r"(a1), "r"(a2), "r"(a3), "r"(b0), "r"(b1));
}

__device__ __forceinline__ void load_chunk(const float* __restrict__ X,
                                           const float* __restrict__ W,
                                           int rowBase, int colBase, int k0,
                                           uint32_t sA, uint32_t sB, int tid) {
    #pragma unroll
    for (int s = 0; s < 4; s++) {
        int q = tid + s * 256;
        int r = q >> 3, ch = q & 7;
        int gRow = rowBase + r;
        int ok = (gRow < N_NODES);
        const float* src = X + (size_t)(ok ? gRow : 0) * EMBED_DIM + k0 + ch * 4;
        cp_async16(sA + r * A_ROW_STRIDE + ch * 16, src, ok ? 16 : 0);
    }
    #pragma unroll
    for (int s = 0; s < 4; s++) {
        int q = tid + s * 256;
        int kr = q >> 5, ch = q & 31;
        const float* src = W + (size_t)(k0 + kr) * EMBED_DIM + colBase + ch * 4;
        cp_async16(sB + kr * B_ROW_STRIDE + ch * 16, src, 16);
    }
}

__global__ __launch_bounds__(256, 1) void gemm_mma_kernel(
    const float* __restrict__ X, const float* __restrict__ W)
{
    extern __shared__ char smem[];
    const uint32_t sbase = smem_u32(smem);
    const int tid = threadIdx.x;
    const int rowBase = blockIdx.x * BM;
    const int colBase = blockIdx.y * BN;

    const int w = tid >> 5, lane = tid & 31;
    const int warpM = w & 1, warpN = w >> 1;   // 2 x 4
    const int g = lane >> 2, c4 = lane & 3;

    float acc[4][4][4];
    #pragma unroll
    for (int i = 0; i < 4; i++)
        #pragma unroll
        for (int j = 0; j < 4; j++)
            #pragma unroll
            for (int r = 0; r < 4; r++) acc[i][j][r] = 0.f;

    load_chunk(X, W, rowBase, colBase, 0, sbase, sbase + A_TILE_BYTES, tid);
    asm volatile("cp.async.commit_group;" ::: "memory");
    load_chunk(X, W, rowBase, colBase, BK,
               sbase + STAGE_BYTES, sbase + STAGE_BYTES + A_TILE_BYTES, tid);
    asm volatile("cp.async.commit_group;" ::: "memory");

    const int NCHUNKS = EMBED_DIM / BK;  // 16
    for (int cidx = 0; cidx < NCHUNKS; cidx++) {
        const int buf = cidx & 1;
        asm volatile("cp.async.wait_group 1;" ::: "memory");
        __syncthreads();

        const char* As = smem + buf * STAGE_BYTES;
        const char* Bs = As + A_TILE_BYTES;
        const int aRow0 = warpM * 64 + g;
        const int bCol0 = warpN * 32 + g;

        #pragma unroll
        for (int ks = 0; ks < 4; ks++) {
            const int k0 = ks * 8;
            uint32_t af[4][4], bf[4][2];
            #pragma unroll
            for (int i = 0; i < 4; i++) {
                const char* base = As + (aRow0 + i * 16) * A_ROW_STRIDE + (k0 + c4) * 4;
                af[i][0] = f2tf32(*(const float*)(base));
                af[i][1] = f2tf32(*(const float*)(base + 8 * A_ROW_STRIDE));
                af[i][2] = f2tf32(*(const float*)(base + 16));
                af[i][3] = f2tf32(*(const float*)(base + 8 * A_ROW_STRIDE + 16));
            }
            #pragma unroll
            for (int j = 0; j < 4; j++) {
                const char* base = Bs + (k0 + c4) * B_ROW_STRIDE + (bCol0 + j * 8) * 4;
                bf[j][0] = f2tf32(*(const float*)(base));
                bf[j][1] = f2tf32(*(const float*)(base + 4 * B_ROW_STRIDE));
            }
            #pragma unroll
            for (int i = 0; i < 4; i++)
                #pragma unroll
                for (int j = 0; j < 4; j++)
                    mma_tf32(acc[i][j][0], acc[i][j][1], acc[i][j][2], acc[i][j][3],
                             af[i][0], af[i][1], af[i][2], af[i][3],
                             bf[j][0], bf[j][1]);
        }

        __syncthreads();
        if (cidx + 2 < NCHUNKS) {
            load_chunk(X, W, rowBase, colBase, (cidx + 2) * BK,
                       sbase + buf * STAGE_BYTES,
                       sbase + buf * STAGE_BYTES + A_TILE_BYTES, tid);
        }
        asm volatile("cp.async.commit_group;" ::: "memory");
    }

    // epilogue: scale by dinv[row], write Hs only
    #pragma unroll
    for (int i = 0; i < 4; i++) {
        #pragma unroll
        for (int half = 0; half < 2; half++) {
            int row = rowBase + warpM * 64 + i * 16 + g + half * 8;
            if (row >= N_NODES) continue;
            float s = g_dinv[row];
            size_t base = (size_t)row * EMBED_DIM + colBase + warpN * 32 + 2 * c4;
            #pragma unroll
            for (int j = 0; j < 4; j++) {
                float2 v;
                v.x = acc[i][j][half * 2 + 0] * s;
                v.y = acc[i][j][half * 2 + 1] * s;
                *reinterpret_cast<float2*>(&g_Hs[base + j * 8]) = v;
            }
        }
    }
}

// -------------------- gather: out[n] = leaky(dinv[n]*(Hs[n] + sum Hs[src]) + b) ------
__global__ __launch_bounds__(256) void gather_kernel(
    const float* __restrict__ b, float* __restrict__ out)
{
    int node = (blockIdx.x * blockDim.x + threadIdx.x) >> 5;
    if (node >= N_NODES) return;
    int lane = threadIdx.x & 31;

    // self-loop term
    const float4* self = reinterpret_cast<const float4*>(&g_Hs[(size_t)node * EMBED_DIM]);
    float4 acc[4];
    #pragma unroll
    for (int i = 0; i < 4; i++) acc[i] = __ldg(&self[i * 32 + lane]);

    int e = g_row_start[node];
    const int end = g_row_start[node + 1];

    // unroll x2 for MLP
    for (; e + 2 <= end; e += 2) {
        int s0 = __ldg(&g_csr_src[e]);
        int s1 = __ldg(&g_csr_src[e + 1]);
        const float4* r0 = reinterpret_cast<const float4*>(&g_Hs[(size_t)s0 * EMBED_DIM]);
        const float4* r1 = reinterpret_cast<const float4*>(&g_Hs[(size_t)s1 * EMBED_DIM]);
        float4 v0[4], v1[4];
        #pragma unroll
        for (int i = 0; i < 4; i++) v0[i] = __ldg(&r0[i * 32 + lane]);
        #pragma unroll
        for (int i = 0; i < 4; i++) v1[i] = __ldg(&r1[i * 32 + lane]);
        #pragma unroll
        for (int i = 0; i < 4; i++) {
            acc[i].x += v0[i].x + v1[i].x;
            acc[i].y += v0[i].y + v1[i].y;
            acc[i].z += v0[i].z + v1[i].z;
            acc[i].w += v0[i].w + v1[i].w;
        }
    }
    if (e < end) {
        int s0 = __ldg(&g_csr_src[e]);
        const float4* r0 = reinterpret_cast<const float4*>(&g_Hs[(size_t)s0 * EMBED_DIM]);
        #pragma unroll
        for (int i = 0; i < 4; i++) {
            float4 v = __ldg(&r0[i * 32 + lane]);
            acc[i].x += v.x; acc[i].y += v.y; acc[i].z += v.z; acc[i].w += v.w;
        }
    }

    const float sc = g_dinv[node];
    const float4* b4 = reinterpret_cast<const float4*>(b);
    float4* o4 = reinterpret_cast<float4*>(&out[(size_t)node * EMBED_DIM]);
    #pragma unroll
    for (int i = 0; i < 4; i++) {
        float4 bb = __ldg(&b4[i * 32 + lane]);
        float4 v;
        float t;
        t = acc[i].x * sc + bb.x; v.x = (t >= 0.f) ? t : NEG_SLOPE * t;
        t = acc[i].y * sc + bb.y; v.y = (t >= 0.f) ? t : NEG_SLOPE * t;
        t = acc[i].z * sc + bb.z; v.z = (t >= 0.f) ? t : NEG_SLOPE * t;
        t = acc[i].w * sc + bb.w; v.w = (t >= 0.f) ? t : NEG_SLOPE * t;
        o4[i * 32 + lane] = v;
    }
}

// -------------------- launch --------------------
extern "C" void kernel_launch(void* const* d_in, const int* in_sizes, int n_in,
                              void* d_out, int out_size) {
    const float* X = (const float*)d_in[0];
    const float* W = (const float*)d_in[1];
    const float* b = (const float*)d_in[2];
    const int* edge = (const int*)d_in[3];
    const int* src = edge;
    const int* dst = edge + N_EDGES;
    float* out = (float*)d_out;

    init_deg_kernel<<<(N_NODES + 255) / 256, 256>>>();
    count_deg_kernel<<<(N_EDGES + 255) / 256, 256>>>(dst);
    dinv_kernel<<<(N_NODES + 255) / 256, 256>>>();
    scan_kernel<<<1, 1024>>>();
    csr_fill_kernel<<<(N_EDGES + 255) / 256, 256>>>(src, dst);

    cudaFuncSetAttribute(gemm_mma_kernel,
                         cudaFuncAttributeMaxDynamicSharedMemorySize, SMEM_TOTAL);
    dim3 ggrid((N_NODES + BM - 1) / BM, EMBED_DIM / BN);
    gemm_mma_kernel<<<ggrid, 256, SMEM_TOTAL>>>(X, W);

    // one warp per node, 8 warps per block
    gather_kernel<<<(N_NODES + 7) / 8, 256>>>(b, out);
}

// round 9
// speedup vs baseline: 4.2355x; 1.2001x over previous
#include <cuda_runtime.h>
#include <cstdint>

#define N_NODES 50000
#define EMBED_DIM 512
#define N_EDGES 800000
#define NEG_SLOPE 0.01f

#define SCAN_BLOCKS 196   // ceil(50000/256)

// -------- scratch (allocation-free: __device__ globals) --------
__device__ float g_Hs[(size_t)N_NODES * EMBED_DIM];  // (X@W) * dinv[row]
__device__ int   g_deg[N_NODES];                     // 1 + in-degree
__device__ float g_dinv[N_NODES];
__device__ int   g_row_start[N_NODES + 1];
__device__ int   g_cursor[N_NODES];
__device__ int   g_csr_src[N_EDGES];
__device__ int   g_blk[SCAN_BLOCKS];
__device__ int   g_blk_pref[SCAN_BLOCKS];

// -------------------- degree --------------------
__global__ void init_deg_kernel() {
    int i = blockIdx.x * blockDim.x + threadIdx.x;
    if (i < N_NODES) g_deg[i] = 1;  // self-loop
}
__global__ void count_deg_kernel(const int* __restrict__ dst) {
    int e = blockIdx.x * blockDim.x + threadIdx.x;
    if (e < N_EDGES) atomicAdd(&g_deg[dst[e]], 1);
}

// -------------------- 3-pass scan of (deg-1) --------------------
// Pass A: per-block sums
__global__ __launch_bounds__(256) void scan_passA() {
    __shared__ int wsum[8];
    int i = blockIdx.x * 256 + threadIdx.x;
    int v = (i < N_NODES) ? (g_deg[i] - 1) : 0;
    #pragma unroll
    for (int o = 16; o > 0; o >>= 1) v += __shfl_down_sync(0xffffffff, v, o);
    if ((threadIdx.x & 31) == 0) wsum[threadIdx.x >> 5] = v;
    __syncthreads();
    if (threadIdx.x < 8) {
        int s = wsum[threadIdx.x];
        #pragma unroll
        for (int o = 4; o > 0; o >>= 1) s += __shfl_down_sync(0xff, s, o);
        if (threadIdx.x == 0) g_blk[blockIdx.x] = s;
    }
}
// Pass B: single block scans the 196 partials (exclusive)
__global__ __launch_bounds__(256) void scan_passB() {
    __shared__ int wsum[8];
    int t = threadIdx.x;
    int v = (t < SCAN_BLOCKS) ? g_blk[t] : 0;
    int lane = t & 31, w = t >> 5;
    // inclusive warp scan
    int inc = v;
    #pragma unroll
    for (int o = 1; o < 32; o <<= 1) {
        int u = __shfl_up_sync(0xffffffff, inc, o);
        if (lane >= o) inc += u;
    }
    if (lane == 31) wsum[w] = inc;
    __syncthreads();
    if (t < 8) {
        int s = wsum[t];
        int si = s;
        #pragma unroll
        for (int o = 1; o < 8; o <<= 1) {
            int u = __shfl_up_sync(0xff, si, o);
            if (t >= o) si += u;
        }
        wsum[t] = si - s;  // exclusive warp offset
    }
    __syncthreads();
    if (t < SCAN_BLOCKS) g_blk_pref[t] = wsum[w] + inc - v;  // exclusive
}
// Pass C: per-block exclusive scan + prefix; also dinv and cursor init
__global__ __launch_bounds__(256) void scan_passC() {
    __shared__ int wsum[8];
    int i = blockIdx.x * 256 + threadIdx.x;
    int deg = (i < N_NODES) ? g_deg[i] : 1;
    int v = deg - 1;
    int lane = threadIdx.x & 31, w = threadIdx.x >> 5;
    int inc = v;
    #pragma unroll
    for (int o = 1; o < 32; o <<= 1) {
        int u = __shfl_up_sync(0xffffffff, inc, o);
        if (lane >= o) inc += u;
    }
    if (lane == 31) wsum[w] = inc;
    __syncthreads();
    if (threadIdx.x < 8) {
        int s = wsum[threadIdx.x];
        int si = s;
        #pragma unroll
        for (int o = 1; o < 8; o <<= 1) {
            int u = __shfl_up_sync(0xff, si, o);
            if (threadIdx.x >= o) si += u;
        }
        wsum[threadIdx.x] = si - s;
    }
    __syncthreads();
    if (i < N_NODES) {
        int ex = g_blk_pref[blockIdx.x] + wsum[w] + inc - v;
        g_row_start[i] = ex;
        g_cursor[i] = ex;
        g_dinv[i] = rsqrtf((float)deg);
    }
    if (i == 0) g_row_start[N_NODES] = N_EDGES;
}

__global__ void csr_fill_kernel(const int* __restrict__ src, const int* __restrict__ dst) {
    int e = blockIdx.x * blockDim.x + threadIdx.x;
    if (e >= N_EDGES) return;
    int d = dst[e];
    int pos = atomicAdd(&g_cursor[d], 1);
    g_csr_src[pos] = src[e];
}

// ==================== mma.sync TF32 GEMM ====================
// Hs = (X @ W) * dinv[row].
#define BM 128
#define BN 128
#define BK 32
#define A_ROW_STRIDE 144
#define B_ROW_STRIDE 544
#define A_TILE_BYTES (BM * A_ROW_STRIDE)
#define B_TILE_BYTES (BK * B_ROW_STRIDE)
#define STAGE_BYTES (A_TILE_BYTES + B_TILE_BYTES)
#define SMEM_TOTAL (2 * STAGE_BYTES)

__device__ __forceinline__ uint32_t smem_u32(const void* p) {
    uint32_t a;
    asm("{ .reg .u64 t; cvta.to.shared.u64 t, %1; cvt.u32.u64 %0, t; }" : "=r"(a) : "l"(p));
    return a;
}
__device__ __forceinline__ void cp_async16(uint32_t dst, const float* src, int sz) {
    asm volatile("cp.async.cg.shared.global [%0], [%1], 16, %2;"
                 :: "r"(dst), "l"(src), "r"(sz));
}
__device__ __forceinline__ uint32_t f2tf32(float v) {
    uint32_t u;
    asm("cvt.rna.tf32.f32 %0, %1;" : "=r"(u) : "f"(v));
    return u;
}
__device__ __forceinline__ void mma_tf32(float& d0, float& d1, float& d2, float& d3,
                                         uint32_t a0, uint32_t a1, uint32_t a2, uint32_t a3,
                                         uint32_t b0, uint32_t b1) {
    asm volatile(
        "mma.sync.aligned.m16n8k8.row.col.f32.tf32.tf32.f32 "
        "{%0,%1,%2,%3}, {%4,%5,%6,%7}, {%8,%9}, {%0,%1,%2,%3};"
        : "+f"(d0), "+f"(d1), "+f"(d2), "+f"(d3)
        : "r"(a0), "r"(a1), "r"(a2), "r"(a3), "r"(b0), "r"(b1));
}

__device__ __forceinline__ void load_chunk(const float* __restrict__ X,
                                           const float* __restrict__ W,
                                           int rowBase, int colBase, int k0,
                                           uint32_t sA, uint32_t sB, int tid) {
    #pragma unroll
    for (int s = 0; s < 4; s++) {
        int q = tid + s * 256;
        int r = q >> 3, ch = q & 7;
        int gRow = rowBase + r;
        int ok = (gRow < N_NODES);
        const float* src = X + (size_t)(ok ? gRow : 0) * EMBED_DIM + k0 + ch * 4;
        cp_async16(sA + r * A_ROW_STRIDE + ch * 16, src, ok ? 16 : 0);
    }
    #pragma unroll
    for (int s = 0; s < 4; s++) {
        int q = tid + s * 256;
        int kr = q >> 5, ch = q & 31;
        const float* src = W + (size_t)(k0 + kr) * EMBED_DIM + colBase + ch * 4;
        cp_async16(sB + kr * B_ROW_STRIDE + ch * 16, src, 16);
    }
}

// grid: (cols=4, rowTiles=391) — col-major fastest so a wave shares A tiles in L2
__global__ __launch_bounds__(256, 1) void gemm_mma_kernel(
    const float* __restrict__ X, const float* __restrict__ W)
{
    extern __shared__ char smem[];
    const uint32_t sbase = smem_u32(smem);
    const int tid = threadIdx.x;
    const int rowBase = blockIdx.y * BM;
    const int colBase = blockIdx.x * BN;

    const int w = tid >> 5, lane = tid & 31;
    const int warpM = w & 1, warpN = w >> 1;   // 2 x 4
    const int g = lane >> 2, c4 = lane & 3;

    float acc[4][4][4];
    #pragma unroll
    for (int i = 0; i < 4; i++)
        #pragma unroll
        for (int j = 0; j < 4; j++)
            #pragma unroll
            for (int r = 0; r < 4; r++) acc[i][j][r] = 0.f;

    load_chunk(X, W, rowBase, colBase, 0, sbase, sbase + A_TILE_BYTES, tid);
    asm volatile("cp.async.commit_group;" ::: "memory");
    load_chunk(X, W, rowBase, colBase, BK,
               sbase + STAGE_BYTES, sbase + STAGE_BYTES + A_TILE_BYTES, tid);
    asm volatile("cp.async.commit_group;" ::: "memory");

    const int NCHUNKS = EMBED_DIM / BK;  // 16
    for (int cidx = 0; cidx < NCHUNKS; cidx++) {
        const int buf = cidx & 1;
        asm volatile("cp.async.wait_group 1;" ::: "memory");
        __syncthreads();

        const char* As = smem + buf * STAGE_BYTES;
        const char* Bs = As + A_TILE_BYTES;
        const int aRow0 = warpM * 64 + g;
        const int bCol0 = warpN * 32 + g;

        #pragma unroll
        for (int ks = 0; ks < 4; ks++) {
            const int k0 = ks * 8;
            uint32_t af[4][4], bf[4][2];
            #pragma unroll
            for (int i = 0; i < 4; i++) {
                const char* base = As + (aRow0 + i * 16) * A_ROW_STRIDE + (k0 + c4) * 4;
                af[i][0] = f2tf32(*(const float*)(base));
                af[i][1] = f2tf32(*(const float*)(base + 8 * A_ROW_STRIDE));
                af[i][2] = f2tf32(*(const float*)(base + 16));
                af[i][3] = f2tf32(*(const float*)(base + 8 * A_ROW_STRIDE + 16));
            }
            #pragma unroll
            for (int j = 0; j < 4; j++) {
                const char* base = Bs + (k0 + c4) * B_ROW_STRIDE + (bCol0 + j * 8) * 4;
                bf[j][0] = f2tf32(*(const float*)(base));
                bf[j][1] = f2tf32(*(const float*)(base + 4 * B_ROW_STRIDE));
            }
            #pragma unroll
            for (int i = 0; i < 4; i++)
                #pragma unroll
                for (int j = 0; j < 4; j++)
                    mma_tf32(acc[i][j][0], acc[i][j][1], acc[i][j][2], acc[i][j][3],
                             af[i][0], af[i][1], af[i][2], af[i][3],
                             bf[j][0], bf[j][1]);
        }

        __syncthreads();
        if (cidx + 2 < NCHUNKS) {
            load_chunk(X, W, rowBase, colBase, (cidx + 2) * BK,
                       sbase + buf * STAGE_BYTES,
                       sbase + buf * STAGE_BYTES + A_TILE_BYTES, tid);
        }
        asm volatile("cp.async.commit_group;" ::: "memory");
    }

    // epilogue: scale by dinv[row], write Hs only
    #pragma unroll
    for (int i = 0; i < 4; i++) {
        #pragma unroll
        for (int half = 0; half < 2; half++) {
            int row = rowBase + warpM * 64 + i * 16 + g + half * 8;
            if (row >= N_NODES) continue;
            float s = g_dinv[row];
            size_t base = (size_t)row * EMBED_DIM + colBase + warpN * 32 + 2 * c4;
            #pragma unroll
            for (int j = 0; j < 4; j++) {
                float2 v;
                v.x = acc[i][j][half * 2 + 0] * s;
                v.y = acc[i][j][half * 2 + 1] * s;
                *reinterpret_cast<float2*>(&g_Hs[base + j * 8]) = v;
            }
        }
    }
}

// -------------------- gather: out[n] = leaky(dinv[n]*(Hs[n] + sum Hs[src]) + b) ------
__global__ __launch_bounds__(256) void gather_kernel(
    const float* __restrict__ b, float* __restrict__ out)
{
    int node = (blockIdx.x * blockDim.x + threadIdx.x) >> 5;
    if (node >= N_NODES) return;
    int lane = threadIdx.x & 31;

    // self-loop term
    const float4* self = reinterpret_cast<const float4*>(&g_Hs[(size_t)node * EMBED_DIM]);
    float4 acc[4];
    #pragma unroll
    for (int i = 0; i < 4; i++) acc[i] = __ldg(&self[i * 32 + lane]);

    int e = g_row_start[node];
    const int end = g_row_start[node + 1];

    for (; e + 2 <= end; e += 2) {
        int s0 = __ldg(&g_csr_src[e]);
        int s1 = __ldg(&g_csr_src[e + 1]);
        const float4* r0 = reinterpret_cast<const float4*>(&g_Hs[(size_t)s0 * EMBED_DIM]);
        const float4* r1 = reinterpret_cast<const float4*>(&g_Hs[(size_t)s1 * EMBED_DIM]);
        float4 v0[4], v1[4];
        #pragma unroll
        for (int i = 0; i < 4; i++) v0[i] = __ldg(&r0[i * 32 + lane]);
        #pragma unroll
        for (int i = 0; i < 4; i++) v1[i] = __ldg(&r1[i * 32 + lane]);
        #pragma unroll
        for (int i = 0; i < 4; i++) {
            acc[i].x += v0[i].x + v1[i].x;
            acc[i].y += v0[i].y + v1[i].y;
            acc[i].z += v0[i].z + v1[i].z;
            acc[i].w += v0[i].w + v1[i].w;
        }
    }
    if (e < end) {
        int s0 = __ldg(&g_csr_src[e]);
        const float4* r0 = reinterpret_cast<const float4*>(&g_Hs[(size_t)s0 * EMBED_DIM]);
        #pragma unroll
        for (int i = 0; i < 4; i++) {
            float4 v = __ldg(&r0[i * 32 + lane]);
            acc[i].x += v.x; acc[i].y += v.y; acc[i].z += v.z; acc[i].w += v.w;
        }
    }

    const float sc = g_dinv[node];
    const float4* b4 = reinterpret_cast<const float4*>(b);
    float4* o4 = reinterpret_cast<float4*>(&out[(size_t)node * EMBED_DIM]);
    #pragma unroll
    for (int i = 0; i < 4; i++) {
        float4 bb = __ldg(&b4[i * 32 + lane]);
        float4 v;
        float t;
        t = acc[i].x * sc + bb.x; v.x = (t >= 0.f) ? t : NEG_SLOPE * t;
        t = acc[i].y * sc + bb.y; v.y = (t >= 0.f) ? t : NEG_SLOPE * t;
        t = acc[i].z * sc + bb.z; v.z = (t >= 0.f) ? t : NEG_SLOPE * t;
        t = acc[i].w * sc + bb.w; v.w = (t >= 0.f) ? t : NEG_SLOPE * t;
        o4[i * 32 + lane] = v;
    }
}

// -------------------- launch --------------------
extern "C" void kernel_launch(void* const* d_in, const int* in_sizes, int n_in,
                              void* d_out, int out_size) {
    const float* X = (const float*)d_in[0];
    const float* W = (const float*)d_in[1];
    const float* b = (const float*)d_in[2];
    const int* edge = (const int*)d_in[3];
    const int* src = edge;
    const int* dst = edge + N_EDGES;
    float* out = (float*)d_out;

    init_deg_kernel<<<(N_NODES + 255) / 256, 256>>>();
    count_deg_kernel<<<(N_EDGES + 255) / 256, 256>>>(dst);
    scan_passA<<<SCAN_BLOCKS, 256>>>();
    scan_passB<<<1, 256>>>();
    scan_passC<<<SCAN_BLOCKS, 256>>>();
    csr_fill_kernel<<<(N_EDGES + 255) / 256, 256>>>(src, dst);

    cudaFuncSetAttribute(gemm_mma_kernel,
                         cudaFuncAttributeMaxDynamicSharedMemorySize, SMEM_TOTAL);
    dim3 ggrid(EMBED_DIM / BN, (N_NODES + BM - 1) / BM);  // col-fastest for A L2 reuse
    gemm_mma_kernel<<<ggrid, 256, SMEM_TOTAL>>>(X, W);

    gather_kernel<<<(N_NODES + 7) / 8, 256>>>(b, out);
}

// round 10
// speedup vs baseline: 5.6893x; 1.3433x over previous
#include <cuda_runtime.h>
#include <cuda_fp16.h>
#include <cstdint>

#define N_NODES 50000
#define EMBED_DIM 512
#define N_EDGES 800000
#define NEG_SLOPE 0.01f

#define SCAN_BLOCKS 196   // ceil(50000/256)

// -------- scratch (allocation-free: __device__ globals) --------
__device__ uint32_t g_Hs_h[(size_t)N_NODES * (EMBED_DIM / 2)];  // fp16x2 packed Hs
__device__ int   g_deg[N_NODES];                     // 1 + in-degree
__device__ float g_dinv[N_NODES];
__device__ int   g_row_start[N_NODES + 1];
__device__ int   g_cursor[N_NODES];
__device__ int   g_csr_src[N_EDGES];
__device__ int   g_blk[SCAN_BLOCKS];
__device__ int   g_blk_pref[SCAN_BLOCKS];

// -------------------- degree --------------------
__global__ void init_deg_kernel() {
    int i = blockIdx.x * blockDim.x + threadIdx.x;
    if (i < N_NODES) g_deg[i] = 1;  // self-loop
}
__global__ void count_deg_kernel(const int* __restrict__ dst) {
    int e = blockIdx.x * blockDim.x + threadIdx.x;
    if (e < N_EDGES) atomicAdd(&g_deg[dst[e]], 1);
}

// -------------------- 3-pass scan of (deg-1) --------------------
__global__ __launch_bounds__(256) void scan_passA() {
    __shared__ int wsum[8];
    int i = blockIdx.x * 256 + threadIdx.x;
    int v = (i < N_NODES) ? (g_deg[i] - 1) : 0;
    #pragma unroll
    for (int o = 16; o > 0; o >>= 1) v += __shfl_down_sync(0xffffffff, v, o);
    if ((threadIdx.x & 31) == 0) wsum[threadIdx.x >> 5] = v;
    __syncthreads();
    if (threadIdx.x < 8) {
        int s = wsum[threadIdx.x];
        #pragma unroll
        for (int o = 4; o > 0; o >>= 1) s += __shfl_down_sync(0xff, s, o);
        if (threadIdx.x == 0) g_blk[blockIdx.x] = s;
    }
}
__global__ __launch_bounds__(256) void scan_passB() {
    __shared__ int wsum[8];
    int t = threadIdx.x;
    int v = (t < SCAN_BLOCKS) ? g_blk[t] : 0;
    int lane = t & 31, w = t >> 5;
    int inc = v;
    #pragma unroll
    for (int o = 1; o < 32; o <<= 1) {
        int u = __shfl_up_sync(0xffffffff, inc, o);
        if (lane >= o) inc += u;
    }
    if (lane == 31) wsum[w] = inc;
    __syncthreads();
    if (t < 8) {
        int s = wsum[t];
        int si = s;
        #pragma unroll
        for (int o = 1; o < 8; o <<= 1) {
            int u = __shfl_up_sync(0xff, si, o);
            if (t >= o) si += u;
        }
        wsum[t] = si - s;
    }
    __syncthreads();
    if (t < SCAN_BLOCKS) g_blk_pref[t] = wsum[w] + inc - v;
}
__global__ __launch_bounds__(256) void scan_passC() {
    __shared__ int wsum[8];
    int i = blockIdx.x * 256 + threadIdx.x;
    int deg = (i < N_NODES) ? g_deg[i] : 1;
    int v = deg - 1;
    int lane = threadIdx.x & 31, w = threadIdx.x >> 5;
    int inc = v;
    #pragma unroll
    for (int o = 1; o < 32; o <<= 1) {
        int u = __shfl_up_sync(0xffffffff, inc, o);
        if (lane >= o) inc += u;
    }
    if (lane == 31) wsum[w] = inc;
    __syncthreads();
    if (threadIdx.x < 8) {
        int s = wsum[threadIdx.x];
        int si = s;
        #pragma unroll
        for (int o = 1; o < 8; o <<= 1) {
            int u = __shfl_up_sync(0xff, si, o);
            if (threadIdx.x >= o) si += u;
        }
        wsum[threadIdx.x] = si - s;
    }
    __syncthreads();
    if (i < N_NODES) {
        int ex = g_blk_pref[blockIdx.x] + wsum[w] + inc - v;
        g_row_start[i] = ex;
        g_cursor[i] = ex;
        g_dinv[i] = rsqrtf((float)deg);
    }
    if (i == 0) g_row_start[N_NODES] = N_EDGES;
}

__global__ void csr_fill_kernel(const int* __restrict__ src, const int* __restrict__ dst) {
    int e = blockIdx.x * blockDim.x + threadIdx.x;
    if (e >= N_EDGES) return;
    int d = dst[e];
    int pos = atomicAdd(&g_cursor[d], 1);
    g_csr_src[pos] = src[e];
}

// ==================== mma.sync TF32 GEMM ====================
#define BM 128
#define BN 128
#define BK 32
#define A_ROW_STRIDE 144
#define B_ROW_STRIDE 544
#define A_TILE_BYTES (BM * A_ROW_STRIDE)
#define B_TILE_BYTES (BK * B_ROW_STRIDE)
#define STAGE_BYTES (A_TILE_BYTES + B_TILE_BYTES)
#define SMEM_TOTAL (2 * STAGE_BYTES)

__device__ __forceinline__ uint32_t smem_u32(const void* p) {
    uint32_t a;
    asm("{ .reg .u64 t; cvta.to.shared.u64 t, %1; cvt.u32.u64 %0, t; }" : "=r"(a) : "l"(p));
    return a;
}
__device__ __forceinline__ void cp_async16(uint32_t dst, const float* src, int sz) {
    asm volatile("cp.async.cg.shared.global [%0], [%1], 16, %2;"
                 :: "r"(dst), "l"(src), "r"(sz));
}
__device__ __forceinline__ uint32_t f2tf32(float v) {
    uint32_t u;
    asm("cvt.rna.tf32.f32 %0, %1;" : "=r"(u) : "f"(v));
    return u;
}
__device__ __forceinline__ void mma_tf32(float& d0, float& d1, float& d2, float& d3,
                                         uint32_t a0, uint32_t a1, uint32_t a2, uint32_t a3,
                                         uint32_t b0, uint32_t b1) {
    asm volatile(
        "mma.sync.aligned.m16n8k8.row.col.f32.tf32.tf32.f32 "
        "{%0,%1,%2,%3}, {%4,%5,%6,%7}, {%8,%9}, {%0,%1,%2,%3};"
        : "+f"(d0), "+f"(d1), "+f"(d2), "+f"(d3)
        : "r"(a0), "r"(a1), "r"(a2), "r"(a3), "r"(b0), "r"(b1));
}

__device__ __forceinline__ void load_chunk(const float* __restrict__ X,
                                           const float* __restrict__ W,
                                           int rowBase, int colBase, int k0,
                                           uint32_t sA, uint32_t sB, int tid) {
    #pragma unroll
    for (int s = 0; s < 4; s++) {
        int q = tid + s * 256;
        int r = q >> 3, ch = q & 7;
        int gRow = rowBase + r;
        int ok = (gRow < N_NODES);
        const float* src = X + (size_t)(ok ? gRow : 0) * EMBED_DIM + k0 + ch * 4;
        cp_async16(sA + r * A_ROW_STRIDE + ch * 16, src, ok ? 16 : 0);
    }
    #pragma unroll
    for (int s = 0; s < 4; s++) {
        int q = tid + s * 256;
        int kr = q >> 5, ch = q & 31;
        const float* src = W + (size_t)(k0 + kr) * EMBED_DIM + colBase + ch * 4;
        cp_async16(sB + kr * B_ROW_STRIDE + ch * 16, src, 16);
    }
}

__global__ __launch_bounds__(256, 2) void gemm_mma_kernel(
    const float* __restrict__ X, const float* __restrict__ W)
{
    extern __shared__ char smem[];
    const uint32_t sbase = smem_u32(smem);
    const int tid = threadIdx.x;
    const int rowBase = blockIdx.y * BM;
    const int colBase = blockIdx.x * BN;

    const int w = tid >> 5, lane = tid & 31;
    const int warpM = w & 1, warpN = w >> 1;   // 2 x 4
    const int g = lane >> 2, c4 = lane & 3;

    float acc[4][4][4];
    #pragma unroll
    for (int i = 0; i < 4; i++)
        #pragma unroll
        for (int j = 0; j < 4; j++)
            #pragma unroll
            for (int r = 0; r < 4; r++) acc[i][j][r] = 0.f;

    load_chunk(X, W, rowBase, colBase, 0, sbase, sbase + A_TILE_BYTES, tid);
    asm volatile("cp.async.commit_group;" ::: "memory");
    load_chunk(X, W, rowBase, colBase, BK,
               sbase + STAGE_BYTES, sbase + STAGE_BYTES + A_TILE_BYTES, tid);
    asm volatile("cp.async.commit_group;" ::: "memory");

    const int NCHUNKS = EMBED_DIM / BK;  // 16
    for (int cidx = 0; cidx < NCHUNKS; cidx++) {
        const int buf = cidx & 1;
        asm volatile("cp.async.wait_group 1;" ::: "memory");
        __syncthreads();

        const char* As = smem + buf * STAGE_BYTES;
        const char* Bs = As + A_TILE_BYTES;
        const int aRow0 = warpM * 64 + g;
        const int bCol0 = warpN * 32 + g;

        #pragma unroll
        for (int ks = 0; ks < 4; ks++) {
            const int k0 = ks * 8;
            uint32_t af[4][4], bf[4][2];
            #pragma unroll
            for (int i = 0; i < 4; i++) {
                const char* base = As + (aRow0 + i * 16) * A_ROW_STRIDE + (k0 + c4) * 4;
                af[i][0] = f2tf32(*(const float*)(base));
                af[i][1] = f2tf32(*(const float*)(base + 8 * A_ROW_STRIDE));
                af[i][2] = f2tf32(*(const float*)(base + 16));
                af[i][3] = f2tf32(*(const float*)(base + 8 * A_ROW_STRIDE + 16));
            }
            #pragma unroll
            for (int j = 0; j < 4; j++) {
                const char* base = Bs + (k0 + c4) * B_ROW_STRIDE + (bCol0 + j * 8) * 4;
                bf[j][0] = f2tf32(*(const float*)(base));
                bf[j][1] = f2tf32(*(const float*)(base + 4 * B_ROW_STRIDE));
            }
            #pragma unroll
            for (int i = 0; i < 4; i++)
                #pragma unroll
                for (int j = 0; j < 4; j++)
                    mma_tf32(acc[i][j][0], acc[i][j][1], acc[i][j][2], acc[i][j][3],
                             af[i][0], af[i][1], af[i][2], af[i][3],
                             bf[j][0], bf[j][1]);
        }

        __syncthreads();
        if (cidx + 2 < NCHUNKS) {
            load_chunk(X, W, rowBase, colBase, (cidx + 2) * BK,
                       sbase + buf * STAGE_BYTES,
                       sbase + buf * STAGE_BYTES + A_TILE_BYTES, tid);
        }
        asm volatile("cp.async.commit_group;" ::: "memory");
    }

    // epilogue: scale by dinv[row], pack to fp16x2, write Hs
    const int hbase = (colBase + warpN * 32) / 2 + c4;  // half2 column index
    #pragma unroll
    for (int i = 0; i < 4; i++) {
        #pragma unroll
        for (int half = 0; half < 2; half++) {
            int row = rowBase + warpM * 64 + i * 16 + g + half * 8;
            if (row >= N_NODES) continue;
            float s = g_dinv[row];
            size_t base = (size_t)row * (EMBED_DIM / 2) + hbase;
            #pragma unroll
            for (int j = 0; j < 4; j++) {
                __half2 h = __floats2half2_rn(acc[i][j][half * 2 + 0] * s,
                                              acc[i][j][half * 2 + 1] * s);
                g_Hs_h[base + j * 4] = *reinterpret_cast<uint32_t*>(&h);
            }
        }
    }
}

// -------------------- gather: out[n] = leaky(dinv[n]*(Hs[n] + sum Hs[src]) + b) ------
__device__ __forceinline__ void acc8(float* a, uint4 v) {
    float2 f;
    f = __half22float2(*reinterpret_cast<__half2*>(&v.x)); a[0] += f.x; a[1] += f.y;
    f = __half22float2(*reinterpret_cast<__half2*>(&v.y)); a[2] += f.x; a[3] += f.y;
    f = __half22float2(*reinterpret_cast<__half2*>(&v.z)); a[4] += f.x; a[5] += f.y;
    f = __half22float2(*reinterpret_cast<__half2*>(&v.w)); a[6] += f.x; a[7] += f.y;
}

__global__ __launch_bounds__(256) void gather_kernel(
    const float* __restrict__ b, float* __restrict__ out)
{
    int node = (blockIdx.x * blockDim.x + threadIdx.x) >> 5;
    if (node >= N_NODES) return;
    int lane = threadIdx.x & 31;

    const uint4* hs = reinterpret_cast<const uint4*>(g_Hs_h);  // 64 uint4 per row

    float acc[16];
    {   // self-loop term
        size_t rb = (size_t)node * 64;
        uint4 v0 = __ldg(&hs[rb + lane]);
        uint4 v1 = __ldg(&hs[rb + 32 + lane]);
        #pragma unroll
        for (int i = 0; i < 16; i++) acc[i] = 0.f;
        acc8(acc, v0);
        acc8(acc + 8, v1);
    }

    int e = g_row_start[node];
    const int end = g_row_start[node + 1];

    for (; e + 2 <= end; e += 2) {
        int s0 = __ldg(&g_csr_src[e]);
        int s1 = __ldg(&g_csr_src[e + 1]);
        size_t r0 = (size_t)s0 * 64, r1 = (size_t)s1 * 64;
        uint4 a0 = __ldg(&hs[r0 + lane]);
        uint4 a1 = __ldg(&hs[r0 + 32 + lane]);
        uint4 b0 = __ldg(&hs[r1 + lane]);
        uint4 b1 = __ldg(&hs[r1 + 32 + lane]);
        acc8(acc, a0); acc8(acc + 8, a1);
        acc8(acc, b0); acc8(acc + 8, b1);
    }
    if (e < end) {
        int s0 = __ldg(&g_csr_src[e]);
        size_t r0 = (size_t)s0 * 64;
        uint4 a0 = __ldg(&hs[r0 + lane]);
        uint4 a1 = __ldg(&hs[r0 + 32 + lane]);
        acc8(acc, a0); acc8(acc + 8, a1);
    }

    const float sc = g_dinv[node];
    const float4* b4 = reinterpret_cast<const float4*>(b);
    float4* o4 = reinterpret_cast<float4*>(&out[(size_t)node * EMBED_DIM]);
    #pragma unroll
    for (int p = 0; p < 2; p++) {
        int u = p * 32 + lane;                  // uint4 column index (0..63)
        #pragma unroll
        for (int q = 0; q < 2; q++) {           // two float4 per uint4-chunk
            float4 bb = __ldg(&b4[u * 2 + q]);
            float4 v;
            float t;
            t = acc[p * 8 + q * 4 + 0] * sc + bb.x; v.x = (t >= 0.f) ? t : NEG_SLOPE * t;
            t = acc[p * 8 + q * 4 + 1] * sc + bb.y; v.y = (t >= 0.f) ? t : NEG_SLOPE * t;
            t = acc[p * 8 + q * 4 + 2] * sc + bb.z; v.z = (t >= 0.f) ? t : NEG_SLOPE * t;
            t = acc[p * 8 + q * 4 + 3] * sc + bb.w; v.w = (t >= 0.f) ? t : NEG_SLOPE * t;
            o4[u * 2 + q] = v;
        }
    }
}

// -------------------- launch --------------------
extern "C" void kernel_launch(void* const* d_in, const int* in_sizes, int n_in,
                              void* d_out, int out_size) {
    const float* X = (const float*)d_in[0];
    const float* W = (const float*)d_in[1];
    const float* b = (const float*)d_in[2];
    const int* edge = (const int*)d_in[3];
    const int* src = edge;
    const int* dst = edge + N_EDGES;
    float* out = (float*)d_out;

    init_deg_kernel<<<(N_NODES + 255) / 256, 256>>>();
    count_deg_kernel<<<(N_EDGES + 255) / 256, 256>>>(dst);
    scan_passA<<<SCAN_BLOCKS, 256>>>();
    scan_passB<<<1, 256>>>();
    scan_passC<<<SCAN_BLOCKS, 256>>>();
    csr_fill_kernel<<<(N_EDGES + 255) / 256, 256>>>(src, dst);

    cudaFuncSetAttribute(gemm_mma_kernel,
                         cudaFuncAttributeMaxDynamicSharedMemorySize, SMEM_TOTAL);
    dim3 ggrid(EMBED_DIM / BN, (N_NODES + BM - 1) / BM);
    gemm_mma_kernel<<<ggrid, 256, SMEM_TOTAL>>>(X, W);

    gather_kernel<<<(N_NODES + 7) / 8, 256>>>(b, out);
}

// round 12
// speedup vs baseline: 6.9978x; 1.2300x over previous
#include <cuda_runtime.h>
#include <cuda_fp16.h>
#include <cstdint>

#define N_NODES 50000
#define EMBED_DIM 512
#define N_EDGES 800000
#define NEG_SLOPE 0.01f

#define SCAN_BLOCKS 196   // ceil(50000/256)

// -------- scratch (allocation-free: __device__ globals) --------
__device__ uint32_t g_Hs_h[(size_t)N_NODES * (EMBED_DIM / 2)];  // fp16x2 packed Hs
__device__ uint32_t g_Xh[(size_t)N_NODES * (EMBED_DIM / 2)];    // fp16x2 packed X
__device__ __half   g_Wh_t[EMBED_DIM * EMBED_DIM];              // W^T as fp16: [n][k]
__device__ int   g_deg[N_NODES];
__device__ float g_dinv[N_NODES];
__device__ int   g_row_start[N_NODES + 1];
__device__ int   g_cursor[N_NODES];
__device__ int   g_csr_src[N_EDGES];
__device__ int   g_blk[SCAN_BLOCKS];
__device__ int   g_blk_pref[SCAN_BLOCKS];

// -------------------- converts --------------------
__global__ __launch_bounds__(256) void convert_x_kernel(const float* __restrict__ X) {
    size_t i = (size_t)blockIdx.x * blockDim.x + threadIdx.x;  // 8 floats per thread
    const size_t total = (size_t)N_NODES * EMBED_DIM / 8;
    if (i >= total) return;
    const float4* x4 = reinterpret_cast<const float4*>(X);
    float4 f0 = __ldg(&x4[2 * i]);
    float4 f1 = __ldg(&x4[2 * i + 1]);
    uint4 o;
    __half2 h;
    h = __floats2half2_rn(f0.x, f0.y); o.x = *reinterpret_cast<uint32_t*>(&h);
    h = __floats2half2_rn(f0.z, f0.w); o.y = *reinterpret_cast<uint32_t*>(&h);
    h = __floats2half2_rn(f1.x, f1.y); o.z = *reinterpret_cast<uint32_t*>(&h);
    h = __floats2half2_rn(f1.z, f1.w); o.w = *reinterpret_cast<uint32_t*>(&h);
    reinterpret_cast<uint4*>(g_Xh)[i] = o;
}

// W[k][n] -> g_Wh_t[n][k] fp16
__global__ void convert_w_kernel(const float* __restrict__ W) {
    __shared__ float t[32][33];
    int bx = blockIdx.x * 32, by = blockIdx.y * 32;  // bx: n-base, by: k-base
    int tx = threadIdx.x, ty = threadIdx.y;
    #pragma unroll
    for (int i = 0; i < 32; i += 8)
        t[ty + i][tx] = W[(size_t)(by + ty + i) * EMBED_DIM + bx + tx];  // t[k'][n']
    __syncthreads();
    #pragma unroll
    for (int i = 0; i < 32; i += 8)  // write n = bx+ty+i, k = by+tx
        g_Wh_t[(size_t)(bx + ty + i) * EMBED_DIM + by + tx] = __float2half_rn(t[tx][ty + i]);
}

// -------------------- degree --------------------
__global__ void init_deg_kernel() {
    int i = blockIdx.x * blockDim.x + threadIdx.x;
    if (i < N_NODES) g_deg[i] = 1;  // self-loop
}
__global__ void count_deg_kernel(const int* __restrict__ dst) {
    int e = blockIdx.x * blockDim.x + threadIdx.x;
    if (e < N_EDGES) atomicAdd(&g_deg[dst[e]], 1);
}

// -------------------- 3-pass scan of (deg-1) --------------------
__global__ __launch_bounds__(256) void scan_passA() {
    __shared__ int wsum[8];
    int i = blockIdx.x * 256 + threadIdx.x;
    int v = (i < N_NODES) ? (g_deg[i] - 1) : 0;
    #pragma unroll
    for (int o = 16; o > 0; o >>= 1) v += __shfl_down_sync(0xffffffff, v, o);
    if ((threadIdx.x & 31) == 0) wsum[threadIdx.x >> 5] = v;
    __syncthreads();
    if (threadIdx.x < 8) {
        int s = wsum[threadIdx.x];
        #pragma unroll
        for (int o = 4; o > 0; o >>= 1) s += __shfl_down_sync(0xff, s, o);
        if (threadIdx.x == 0) g_blk[blockIdx.x] = s;
    }
}
__global__ __launch_bounds__(256) void scan_passB() {
    __shared__ int wsum[8];
    int t = threadIdx.x;
    int v = (t < SCAN_BLOCKS) ? g_blk[t] : 0;
    int lane = t & 31, w = t >> 5;
    int inc = v;
    #pragma unroll
    for (int o = 1; o < 32; o <<= 1) {
        int u = __shfl_up_sync(0xffffffff, inc, o);
        if (lane >= o) inc += u;
    }
    if (lane == 31) wsum[w] = inc;
    __syncthreads();
    if (t < 8) {
        int s = wsum[t];
        int si = s;
        #pragma unroll
        for (int o = 1; o < 8; o <<= 1) {
            int u = __shfl_up_sync(0xff, si, o);
            if (t >= o) si += u;
        }
        wsum[t] = si - s;
    }
    __syncthreads();
    if (t < SCAN_BLOCKS) g_blk_pref[t] = wsum[w] + inc - v;
}
__global__ __launch_bounds__(256) void scan_passC() {
    __shared__ int wsum[8];
    int i = blockIdx.x * 256 + threadIdx.x;
    int deg = (i < N_NODES) ? g_deg[i] : 1;
    int v = deg - 1;
    int lane = threadIdx.x & 31, w = threadIdx.x >> 5;
    int inc = v;
    #pragma unroll
    for (int o = 1; o < 32; o <<= 1) {
        int u = __shfl_up_sync(0xffffffff, inc, o);
        if (lane >= o) inc += u;
    }
    if (lane == 31) wsum[w] = inc;
    __syncthreads();
    if (threadIdx.x < 8) {
        int s = wsum[threadIdx.x];
        int si = s;
        #pragma unroll
        for (int o = 1; o < 8; o <<= 1) {
            int u = __shfl_up_sync(0xff, si, o);
            if (threadIdx.x >= o) si += u;
        }
        wsum[threadIdx.x] = si - s;
    }
    __syncthreads();
    if (i < N_NODES) {
        int ex = g_blk_pref[blockIdx.x] + wsum[w] + inc - v;
        g_row_start[i] = ex;
        g_cursor[i] = ex;
        g_dinv[i] = rsqrtf((float)deg);
    }
    if (i == 0) g_row_start[N_NODES] = N_EDGES;
}

__global__ void csr_fill_kernel(const int* __restrict__ src, const int* __restrict__ dst) {
    int e = blockIdx.x * blockDim.x + threadIdx.x;
    if (e >= N_EDGES) return;
    int d = dst[e];
    int pos = atomicAdd(&g_cursor[d], 1);
    g_csr_src[pos] = src[e];
}

// ==================== fp16 mma.sync GEMM (m16n8k16) ====================
// Hs = (X @ W) * dinv[row], inputs fp16, accum fp32.
#define BM 128
#define BN 128
#define BK 64                       // halves per chunk
#define T_ROW_STRIDE 144            // 128B data + 16B pad (16-aligned, conflict-free)
#define A_TILE_BYTES (BM * T_ROW_STRIDE)       // 18432
#define B_TILE_BYTES (BN * T_ROW_STRIDE)       // 18432
#define STAGE_BYTES (A_TILE_BYTES + B_TILE_BYTES)  // 36864
#define SMEM_TOTAL (2 * STAGE_BYTES)               // 73728

__device__ __forceinline__ uint32_t smem_u32(const void* p) {
    uint32_t a;
    asm("{ .reg .u64 t; cvta.to.shared.u64 t, %1; cvt.u32.u64 %0, t; }" : "=r"(a) : "l"(p));
    return a;
}
__device__ __forceinline__ void cp_async16(uint32_t dst, const void* src, int sz) {
    asm volatile("cp.async.cg.shared.global [%0], [%1], 16, %2;"
                 :: "r"(dst), "l"(src), "r"(sz));
}
__device__ __forceinline__ void mma_f16(float& d0, float& d1, float& d2, float& d3,
                                        uint32_t a0, uint32_t a1, uint32_t a2, uint32_t a3,
                                        uint32_t b0, uint32_t b1) {
    asm volatile(
        "mma.sync.aligned.m16n8k16.row.col.f32.f16.f16.f32 "
        "{%0,%1,%2,%3}, {%4,%5,%6,%7}, {%8,%9}, {%0,%1,%2,%3};"
        : "+f"(d0), "+f"(d1), "+f"(d2), "+f"(d3)
        : "r"(a0), "r"(a1), "r"(a2), "r"(a3), "r"(b0), "r"(b1));
}

// k0 in halves. A: g_Xh rows [rowBase,+128). B: g_Wh_t rows [colBase,+128).
__device__ __forceinline__ void load_chunk(int rowBase, int colBase, int k0,
                                           uint32_t sA, uint32_t sB, int tid) {
    const __half* Xh = reinterpret_cast<const __half*>(g_Xh);
    #pragma unroll
    for (int s = 0; s < 4; s++) {
        int q = tid + s * 256;
        int r = q >> 3, ch = q & 7;          // row, 16B chunk (8 halves)
        int gRow = rowBase + r;
        int ok = (gRow < N_NODES);
        const __half* src = Xh + (size_t)(ok ? gRow : 0) * EMBED_DIM + k0 + ch * 8;
        cp_async16(sA + r * T_ROW_STRIDE + ch * 16, src, ok ? 16 : 0);
    }
    #pragma unroll
    for (int s = 0; s < 4; s++) {
        int q = tid + s * 256;
        int n = q >> 3, ch = q & 7;
        const __half* src = g_Wh_t + (size_t)(colBase + n) * EMBED_DIM + k0 + ch * 8;
        cp_async16(sB + n * T_ROW_STRIDE + ch * 16, src, 16);
    }
}

__global__ __launch_bounds__(256, 2) void gemm_mma_kernel()
{
    extern __shared__ char smem[];
    const uint32_t sbase = smem_u32(smem);
    const int tid = threadIdx.x;
    const int rowBase = blockIdx.y * BM;
    const int colBase = blockIdx.x * BN;

    const int w = tid >> 5, lane = tid & 31;
    const int warpM = w & 1, warpN = w >> 1;   // 2 x 4
    const int g = lane >> 2, c4 = lane & 3;

    float acc[4][4][4];
    #pragma unroll
    for (int i = 0; i < 4; i++)
        #pragma unroll
        for (int j = 0; j < 4; j++)
            #pragma unroll
            for (int r = 0; r < 4; r++) acc[i][j][r] = 0.f;

    load_chunk(rowBase, colBase, 0, sbase, sbase + A_TILE_BYTES, tid);
    asm volatile("cp.async.commit_group;" ::: "memory");
    load_chunk(rowBase, colBase, BK,
               sbase + STAGE_BYTES, sbase + STAGE_BYTES + A_TILE_BYTES, tid);
    asm volatile("cp.async.commit_group;" ::: "memory");

    const int NCHUNKS = EMBED_DIM / BK;  // 8
    for (int cidx = 0; cidx < NCHUNKS; cidx++) {
        const int buf = cidx & 1;
        asm volatile("cp.async.wait_group 1;" ::: "memory");
        __syncthreads();

        const char* As = smem + buf * STAGE_BYTES;
        const char* Bs = As + A_TILE_BYTES;
        const int aRow0 = warpM * 64 + g;
        const int bCol0 = warpN * 32 + g;

        #pragma unroll
        for (int ks = 0; ks < 4; ks++) {           // k16 steps within 64
            const int k0 = ks * 16;                // halves
            uint32_t af[4][4], bf[4][2];
            #pragma unroll
            for (int i = 0; i < 4; i++) {
                const char* base = As + (aRow0 + i * 16) * T_ROW_STRIDE + (k0 + 2 * c4) * 2;
                af[i][0] = *(const uint32_t*)(base);
                af[i][1] = *(const uint32_t*)(base + 8 * T_ROW_STRIDE);
                af[i][2] = *(const uint32_t*)(base + 16);
                af[i][3] = *(const uint32_t*)(base + 8 * T_ROW_STRIDE + 16);
            }
            #pragma unroll
            for (int j = 0; j < 4; j++) {
                const char* base = Bs + (bCol0 + j * 8) * T_ROW_STRIDE + (k0 + 2 * c4) * 2;
                bf[j][0] = *(const uint32_t*)(base);
                bf[j][1] = *(const uint32_t*)(base + 16);
            }
            #pragma unroll
            for (int i = 0; i < 4; i++)
                #pragma unroll
                for (int j = 0; j < 4; j++)
                    mma_f16(acc[i][j][0], acc[i][j][1], acc[i][j][2], acc[i][j][3],
                            af[i][0], af[i][1], af[i][2], af[i][3],
                            bf[j][0], bf[j][1]);
        }

        __syncthreads();
        if (cidx + 2 < NCHUNKS) {
            load_chunk(rowBase, colBase, (cidx + 2) * BK,
                       sbase + buf * STAGE_BYTES,
                       sbase + buf * STAGE_BYTES + A_TILE_BYTES, tid);
        }
        asm volatile("cp.async.commit_group;" ::: "memory");
    }

    // epilogue: scale by dinv[row], pack to fp16x2, write Hs
    const int hbase = (colBase + warpN * 32) / 2 + c4;  // half2 column index
    #pragma unroll
    for (int i = 0; i < 4; i++) {
        #pragma unroll
        for (int half = 0; half < 2; half++) {
            int row = rowBase + warpM * 64 + i * 16 + g + half * 8;
            if (row >= N_NODES) continue;
            float s = g_dinv[row];
            size_t base = (size_t)row * (EMBED_DIM / 2) + hbase;
            #pragma unroll
            for (int j = 0; j < 4; j++) {
                __half2 h = __floats2half2_rn(acc[i][j][half * 2 + 0] * s,
                                              acc[i][j][half * 2 + 1] * s);
                g_Hs_h[base + j * 4] = *reinterpret_cast<uint32_t*>(&h);
            }
        }
    }
}

// -------------------- gather: out[n] = leaky(dinv[n]*(Hs[n] + sum Hs[src]) + b) ------
__device__ __forceinline__ void acc8(float* a, uint4 v) {
    float2 f;
    f = __half22float2(*reinterpret_cast<__half2*>(&v.x)); a[0] += f.x; a[1] += f.y;
    f = __half22float2(*reinterpret_cast<__half2*>(&v.y)); a[2] += f.x; a[3] += f.y;
    f = __half22float2(*reinterpret_cast<__half2*>(&v.z)); a[4] += f.x; a[5] += f.y;
    f = __half22float2(*reinterpret_cast<__half2*>(&v.w)); a[6] += f.x; a[7] += f.y;
}

__global__ __launch_bounds__(256) void gather_kernel(
    const float* __restrict__ b, float* __restrict__ out)
{
    int node = (blockIdx.x * blockDim.x + threadIdx.x) >> 5;
    if (node >= N_NODES) return;
    int lane = threadIdx.x & 31;

    const uint4* hs = reinterpret_cast<const uint4*>(g_Hs_h);  // 64 uint4 per row

    float acc[16];
    {   // self-loop term
        size_t rb = (size_t)node * 64;
        uint4 v0 = __ldg(&hs[rb + lane]);
        uint4 v1 = __ldg(&hs[rb + 32 + lane]);
        #pragma unroll
        for (int i = 0; i < 16; i++) acc[i] = 0.f;
        acc8(acc, v0);
        acc8(acc + 8, v1);
    }

    int e = g_row_start[node];
    const int end = g_row_start[node + 1];

    for (; e + 2 <= end; e += 2) {
        int s0 = __ldg(&g_csr_src[e]);
        int s1 = __ldg(&g_csr_src[e + 1]);
        size_t r0 = (size_t)s0 * 64, r1 = (size_t)s1 * 64;
        uint4 a0 = __ldg(&hs[r0 + lane]);
        uint4 a1 = __ldg(&hs[r0 + 32 + lane]);
        uint4 b0 = __ldg(&hs[r1 + lane]);
        uint4 b1 = __ldg(&hs[r1 + 32 + lane]);
        acc8(acc, a0); acc8(acc + 8, a1);
        acc8(acc, b0); acc8(acc + 8, b1);
    }
    if (e < end) {
        int s0 = __ldg(&g_csr_src[e]);
        size_t r0 = (size_t)s0 * 64;
        uint4 a0 = __ldg(&hs[r0 + lane]);
        uint4 a1 = __ldg(&hs[r0 + 32 + lane]);
        acc8(acc, a0); acc8(acc + 8, a1);
    }

    const float sc = g_dinv[node];
    const float4* b4 = reinterpret_cast<const float4*>(b);
    float4* o4 = reinterpret_cast<float4*>(&out[(size_t)node * EMBED_DIM]);
    #pragma unroll
    for (int p = 0; p < 2; p++) {
        int u = p * 32 + lane;
        #pragma unroll
        for (int q = 0; q < 2; q++) {
            float4 bb = __ldg(&b4[u * 2 + q]);
            float4 v;
            float t;
            t = acc[p * 8 + q * 4 + 0] * sc + bb.x; v.x = (t >= 0.f) ? t : NEG_SLOPE * t;
            t = acc[p * 8 + q * 4 + 1] * sc + bb.y; v.y = (t >= 0.f) ? t : NEG_SLOPE * t;
            t = acc[p * 8 + q * 4 + 2] * sc + bb.z; v.z = (t >= 0.f) ? t : NEG_SLOPE * t;
            t = acc[p * 8 + q * 4 + 3] * sc + bb.w; v.w = (t >= 0.f) ? t : NEG_SLOPE * t;
            o4[u * 2 + q] = v;
        }
    }
}

// -------------------- launch --------------------
extern "C" void kernel_launch(void* const* d_in, const int* in_sizes, int n_in,
                              void* d_out, int out_size) {
    const float* X = (const float*)d_in[0];
    const float* W = (const float*)d_in[1];
    const float* b = (const float*)d_in[2];
    const int* edge = (const int*)d_in[3];
    const int* src = edge;
    const int* dst = edge + N_EDGES;
    float* out = (float*)d_out;

    // converts (GEMM inputs)
    size_t cx_threads = (size_t)N_NODES * EMBED_DIM / 8;
    convert_x_kernel<<<(unsigned)((cx_threads + 255) / 256), 256>>>(X);
    convert_w_kernel<<<dim3(16, 16), dim3(32, 8)>>>(W);

    // degree + CSR
    init_deg_kernel<<<(N_NODES + 255) / 256, 256>>>();
    count_deg_kernel<<<(N_EDGES + 255) / 256, 256>>>(dst);
    scan_passA<<<SCAN_BLOCKS, 256>>>();
    scan_passB<<<1, 256>>>();
    scan_passC<<<SCAN_BLOCKS, 256>>>();
    csr_fill_kernel<<<(N_EDGES + 255) / 256, 256>>>(src, dst);

    cudaFuncSetAttribute(gemm_mma_kernel,
                         cudaFuncAttributeMaxDynamicSharedMemorySize, SMEM_TOTAL);
    dim3 ggrid(EMBED_DIM / BN, (N_NODES + BM - 1) / BM);
    gemm_mma_kernel<<<ggrid, 256, SMEM_TOTAL>>>();

    gather_kernel<<<(N_NODES + 7) / 8, 256>>>(b, out);
}

// round 13
// speedup vs baseline: 7.5106x; 1.0733x over previous
#include <cuda_runtime.h>
#include <cuda_fp16.h>
#include <cstdint>

#define N_NODES 50000
#define EMBED_DIM 512
#define N_EDGES 800000
#define NEG_SLOPE 0.01f

#define SCAN_BLOCKS 196   // ceil(50000/256)

// -------- scratch (allocation-free: __device__ globals) --------
__device__ uint32_t g_Hs_h[(size_t)N_NODES * (EMBED_DIM / 2)];  // fp16x2 packed H (unscaled)
__device__ uint32_t g_Xh[(size_t)N_NODES * (EMBED_DIM / 2)];    // fp16x2 packed X
__device__ __half   g_Wh_t[EMBED_DIM * EMBED_DIM];              // W^T as fp16: [n][k]
__device__ int   g_deg[N_NODES];
__device__ float g_dinv[N_NODES];
__device__ int   g_row_start[N_NODES + 1];
__device__ int   g_cursor[N_NODES];
__device__ int   g_csr_src[N_EDGES];
__device__ int   g_blk[SCAN_BLOCKS];
__device__ int   g_blk_pref[SCAN_BLOCKS];

// -------------------- converts --------------------
__global__ __launch_bounds__(256) void convert_x_kernel(const float* __restrict__ X) {
    size_t i = (size_t)blockIdx.x * blockDim.x + threadIdx.x;  // 8 floats per thread
    const size_t total = (size_t)N_NODES * EMBED_DIM / 8;
    if (i >= total) return;
    const float4* x4 = reinterpret_cast<const float4*>(X);
    float4 f0 = __ldg(&x4[2 * i]);
    float4 f1 = __ldg(&x4[2 * i + 1]);
    uint4 o;
    __half2 h;
    h = __floats2half2_rn(f0.x, f0.y); o.x = *reinterpret_cast<uint32_t*>(&h);
    h = __floats2half2_rn(f0.z, f0.w); o.y = *reinterpret_cast<uint32_t*>(&h);
    h = __floats2half2_rn(f1.x, f1.y); o.z = *reinterpret_cast<uint32_t*>(&h);
    h = __floats2half2_rn(f1.z, f1.w); o.w = *reinterpret_cast<uint32_t*>(&h);
    reinterpret_cast<uint4*>(g_Xh)[i] = o;
}

// W[k][n] -> g_Wh_t[n][k] fp16
__global__ void convert_w_kernel(const float* __restrict__ W) {
    __shared__ float t[32][33];
    int bx = blockIdx.x * 32, by = blockIdx.y * 32;  // bx: n-base, by: k-base
    int tx = threadIdx.x, ty = threadIdx.y;
    #pragma unroll
    for (int i = 0; i < 32; i += 8)
        t[ty + i][tx] = W[(size_t)(by + ty + i) * EMBED_DIM + bx + tx];
    __syncthreads();
    #pragma unroll
    for (int i = 0; i < 32; i += 8)
        g_Wh_t[(size_t)(bx + ty + i) * EMBED_DIM + by + tx] = __float2half_rn(t[tx][ty + i]);
}

// -------------------- degree --------------------
__global__ void init_deg_kernel() {
    int i = blockIdx.x * blockDim.x + threadIdx.x;
    if (i < N_NODES) g_deg[i] = 1;  // self-loop
}
__global__ void count_deg_kernel(const int* __restrict__ dst) {
    int e = blockIdx.x * blockDim.x + threadIdx.x;
    if (e < N_EDGES) atomicAdd(&g_deg[dst[e]], 1);
}

// -------------------- 3-pass scan of (deg-1) --------------------
__global__ __launch_bounds__(256) void scan_passA() {
    __shared__ int wsum[8];
    int i = blockIdx.x * 256 + threadIdx.x;
    int v = (i < N_NODES) ? (g_deg[i] - 1) : 0;
    #pragma unroll
    for (int o = 16; o > 0; o >>= 1) v += __shfl_down_sync(0xffffffff, v, o);
    if ((threadIdx.x & 31) == 0) wsum[threadIdx.x >> 5] = v;
    __syncthreads();
    if (threadIdx.x < 8) {
        int s = wsum[threadIdx.x];
        #pragma unroll
        for (int o = 4; o > 0; o >>= 1) s += __shfl_down_sync(0xff, s, o);
        if (threadIdx.x == 0) g_blk[blockIdx.x] = s;
    }
}
__global__ __launch_bounds__(256) void scan_passB() {
    __shared__ int wsum[8];
    int t = threadIdx.x;
    int v = (t < SCAN_BLOCKS) ? g_blk[t] : 0;
    int lane = t & 31, w = t >> 5;
    int inc = v;
    #pragma unroll
    for (int o = 1; o < 32; o <<= 1) {
        int u = __shfl_up_sync(0xffffffff, inc, o);
        if (lane >= o) inc += u;
    }
    if (lane == 31) wsum[w] = inc;
    __syncthreads();
    if (t < 8) {
        int s = wsum[t];
        int si = s;
        #pragma unroll
        for (int o = 1; o < 8; o <<= 1) {
            int u = __shfl_up_sync(0xff, si, o);
            if (t >= o) si += u;
        }
        wsum[t] = si - s;
    }
    __syncthreads();
    if (t < SCAN_BLOCKS) g_blk_pref[t] = wsum[w] + inc - v;
}
__global__ __launch_bounds__(256) void scan_passC() {
    __shared__ int wsum[8];
    int i = blockIdx.x * 256 + threadIdx.x;
    int deg = (i < N_NODES) ? g_deg[i] : 1;
    int v = deg - 1;
    int lane = threadIdx.x & 31, w = threadIdx.x >> 5;
    int inc = v;
    #pragma unroll
    for (int o = 1; o < 32; o <<= 1) {
        int u = __shfl_up_sync(0xffffffff, inc, o);
        if (lane >= o) inc += u;
    }
    if (lane == 31) wsum[w] = inc;
    __syncthreads();
    if (threadIdx.x < 8) {
        int s = wsum[threadIdx.x];
        int si = s;
        #pragma unroll
        for (int o = 1; o < 8; o <<= 1) {
            int u = __shfl_up_sync(0xff, si, o);
            if (threadIdx.x >= o) si += u;
        }
        wsum[threadIdx.x] = si - s;
    }
    __syncthreads();
    if (i < N_NODES) {
        int ex = g_blk_pref[blockIdx.x] + wsum[w] + inc - v;
        g_row_start[i] = ex;
        g_cursor[i] = ex;
        g_dinv[i] = rsqrtf((float)deg);
    }
    if (i == 0) g_row_start[N_NODES] = N_EDGES;
}

__global__ void csr_fill_kernel(const int* __restrict__ src, const int* __restrict__ dst) {
    int e = blockIdx.x * blockDim.x + threadIdx.x;
    if (e >= N_EDGES) return;
    int d = dst[e];
    int pos = atomicAdd(&g_cursor[d], 1);
    g_csr_src[pos] = src[e];
}

// ==================== fp16 mma.sync GEMM (m16n8k16) ====================
// H = X @ W, fp16 in, fp32 accum, fp16 out (unscaled).
#define BM 128
#define BN 128
#define BK 64
#define T_ROW_STRIDE 144
#define A_TILE_BYTES (BM * T_ROW_STRIDE)
#define B_TILE_BYTES (BN * T_ROW_STRIDE)
#define STAGE_BYTES (A_TILE_BYTES + B_TILE_BYTES)
#define SMEM_TOTAL (2 * STAGE_BYTES)

__device__ __forceinline__ uint32_t smem_u32(const void* p) {
    uint32_t a;
    asm("{ .reg .u64 t; cvta.to.shared.u64 t, %1; cvt.u32.u64 %0, t; }" : "=r"(a) : "l"(p));
    return a;
}
__device__ __forceinline__ void cp_async16(uint32_t dst, const void* src, int sz) {
    asm volatile("cp.async.cg.shared.global [%0], [%1], 16, %2;"
                 :: "r"(dst), "l"(src), "r"(sz));
}
__device__ __forceinline__ void mma_f16(float& d0, float& d1, float& d2, float& d3,
                                        uint32_t a0, uint32_t a1, uint32_t a2, uint32_t a3,
                                        uint32_t b0, uint32_t b1) {
    asm volatile(
        "mma.sync.aligned.m16n8k16.row.col.f32.f16.f16.f32 "
        "{%0,%1,%2,%3}, {%4,%5,%6,%7}, {%8,%9}, {%0,%1,%2,%3};"
        : "+f"(d0), "+f"(d1), "+f"(d2), "+f"(d3)
        : "r"(a0), "r"(a1), "r"(a2), "r"(a3), "r"(b0), "r"(b1));
}

__device__ __forceinline__ void load_chunk(int rowBase, int colBase, int k0,
                                           uint32_t sA, uint32_t sB, int tid) {
    const __half* Xh = reinterpret_cast<const __half*>(g_Xh);
    #pragma unroll
    for (int s = 0; s < 4; s++) {
        int q = tid + s * 256;
        int r = q >> 3, ch = q & 7;
        int gRow = rowBase + r;
        int ok = (gRow < N_NODES);
        const __half* src = Xh + (size_t)(ok ? gRow : 0) * EMBED_DIM + k0 + ch * 8;
        cp_async16(sA + r * T_ROW_STRIDE + ch * 16, src, ok ? 16 : 0);
    }
    #pragma unroll
    for (int s = 0; s < 4; s++) {
        int q = tid + s * 256;
        int n = q >> 3, ch = q & 7;
        const __half* src = g_Wh_t + (size_t)(colBase + n) * EMBED_DIM + k0 + ch * 8;
        cp_async16(sB + n * T_ROW_STRIDE + ch * 16, src, 16);
    }
}

__global__ __launch_bounds__(256, 2) void gemm_mma_kernel()
{
    extern __shared__ char smem[];
    const uint32_t sbase = smem_u32(smem);
    const int tid = threadIdx.x;
    const int rowBase = blockIdx.y * BM;
    const int colBase = blockIdx.x * BN;

    const int w = tid >> 5, lane = tid & 31;
    const int warpM = w & 1, warpN = w >> 1;
    const int g = lane >> 2, c4 = lane & 3;

    float acc[4][4][4];
    #pragma unroll
    for (int i = 0; i < 4; i++)
        #pragma unroll
        for (int j = 0; j < 4; j++)
            #pragma unroll
            for (int r = 0; r < 4; r++) acc[i][j][r] = 0.f;

    load_chunk(rowBase, colBase, 0, sbase, sbase + A_TILE_BYTES, tid);
    asm volatile("cp.async.commit_group;" ::: "memory");
    load_chunk(rowBase, colBase, BK,
               sbase + STAGE_BYTES, sbase + STAGE_BYTES + A_TILE_BYTES, tid);
    asm volatile("cp.async.commit_group;" ::: "memory");

    const int NCHUNKS = EMBED_DIM / BK;  // 8
    for (int cidx = 0; cidx < NCHUNKS; cidx++) {
        const int buf = cidx & 1;
        asm volatile("cp.async.wait_group 1;" ::: "memory");
        __syncthreads();

        const char* As = smem + buf * STAGE_BYTES;
        const char* Bs = As + A_TILE_BYTES;
        const int aRow0 = warpM * 64 + g;
        const int bCol0 = warpN * 32 + g;

        #pragma unroll
        for (int ks = 0; ks < 4; ks++) {
            const int k0 = ks * 16;
            uint32_t af[4][4], bf[4][2];
            #pragma unroll
            for (int i = 0; i < 4; i++) {
                const char* base = As + (aRow0 + i * 16) * T_ROW_STRIDE + (k0 + 2 * c4) * 2;
                af[i][0] = *(const uint32_t*)(base);
                af[i][1] = *(const uint32_t*)(base + 8 * T_ROW_STRIDE);
                af[i][2] = *(const uint32_t*)(base + 16);
                af[i][3] = *(const uint32_t*)(base + 8 * T_ROW_STRIDE + 16);
            }
            #pragma unroll
            for (int j = 0; j < 4; j++) {
                const char* base = Bs + (bCol0 + j * 8) * T_ROW_STRIDE + (k0 + 2 * c4) * 2;
                bf[j][0] = *(const uint32_t*)(base);
                bf[j][1] = *(const uint32_t*)(base + 16);
            }
            #pragma unroll
            for (int i = 0; i < 4; i++)
                #pragma unroll
                for (int j = 0; j < 4; j++)
                    mma_f16(acc[i][j][0], acc[i][j][1], acc[i][j][2], acc[i][j][3],
                            af[i][0], af[i][1], af[i][2], af[i][3],
                            bf[j][0], bf[j][1]);
        }

        __syncthreads();
        if (cidx + 2 < NCHUNKS) {
            load_chunk(rowBase, colBase, (cidx + 2) * BK,
                       sbase + buf * STAGE_BYTES,
                       sbase + buf * STAGE_BYTES + A_TILE_BYTES, tid);
        }
        asm volatile("cp.async.commit_group;" ::: "memory");
    }

    // epilogue: pack raw H to fp16x2 (no dinv — applied in gather)
    const int hbase = (colBase + warpN * 32) / 2 + c4;
    #pragma unroll
    for (int i = 0; i < 4; i++) {
        #pragma unroll
        for (int half = 0; half < 2; half++) {
            int row = rowBase + warpM * 64 + i * 16 + g + half * 8;
            if (row >= N_NODES) continue;
            size_t base = (size_t)row * (EMBED_DIM / 2) + hbase;
            #pragma unroll
            for (int j = 0; j < 4; j++) {
                __half2 h = __floats2half2_rn(acc[i][j][half * 2 + 0],
                                              acc[i][j][half * 2 + 1]);
                g_Hs_h[base + j * 4] = *reinterpret_cast<uint32_t*>(&h);
            }
        }
    }
}

// ---- gather: out[n] = leaky(dinv[n]*(H[n]*dinv[n] + sum H[s]*dinv[s]) + b) ----
__device__ __forceinline__ void acc8s(float* a, uint4 v, float s) {
    float2 f;
    f = __half22float2(*reinterpret_cast<__half2*>(&v.x)); a[0] = fmaf(f.x, s, a[0]); a[1] = fmaf(f.y, s, a[1]);
    f = __half22float2(*reinterpret_cast<__half2*>(&v.y)); a[2] = fmaf(f.x, s, a[2]); a[3] = fmaf(f.y, s, a[3]);
    f = __half22float2(*reinterpret_cast<__half2*>(&v.z)); a[4] = fmaf(f.x, s, a[4]); a[5] = fmaf(f.y, s, a[5]);
    f = __half22float2(*reinterpret_cast<__half2*>(&v.w)); a[6] = fmaf(f.x, s, a[6]); a[7] = fmaf(f.y, s, a[7]);
}

__global__ __launch_bounds__(256) void gather_kernel(
    const float* __restrict__ b, float* __restrict__ out)
{
    int node = (blockIdx.x * blockDim.x + threadIdx.x) >> 5;
    if (node >= N_NODES) return;
    int lane = threadIdx.x & 31;

    const uint4* hs = reinterpret_cast<const uint4*>(g_Hs_h);  // 64 uint4 per row
    const float sc = g_dinv[node];

    float acc[16];
    #pragma unroll
    for (int i = 0; i < 16; i++) acc[i] = 0.f;
    {   // self-loop term: H[n] * dinv[n]
        size_t rb = (size_t)node * 64;
        uint4 v0 = __ldg(&hs[rb + lane]);
        uint4 v1 = __ldg(&hs[rb + 32 + lane]);
        acc8s(acc, v0, sc);
        acc8s(acc + 8, v1, sc);
    }

    int e = g_row_start[node];
    const int end = g_row_start[node + 1];

    for (; e + 2 <= end; e += 2) {
        int s0 = __ldg(&g_csr_src[e]);
        int s1 = __ldg(&g_csr_src[e + 1]);
        float d0 = __ldg(&g_dinv[s0]);
        float d1 = __ldg(&g_dinv[s1]);
        size_t r0 = (size_t)s0 * 64, r1 = (size_t)s1 * 64;
        uint4 a0 = __ldg(&hs[r0 + lane]);
        uint4 a1 = __ldg(&hs[r0 + 32 + lane]);
        uint4 b0 = __ldg(&hs[r1 + lane]);
        uint4 b1 = __ldg(&hs[r1 + 32 + lane]);
        acc8s(acc, a0, d0); acc8s(acc + 8, a1, d0);
        acc8s(acc, b0, d1); acc8s(acc + 8, b1, d1);
    }
    if (e < end) {
        int s0 = __ldg(&g_csr_src[e]);
        float d0 = __ldg(&g_dinv[s0]);
        size_t r0 = (size_t)s0 * 64;
        uint4 a0 = __ldg(&hs[r0 + lane]);
        uint4 a1 = __ldg(&hs[r0 + 32 + lane]);
        acc8s(acc, a0, d0); acc8s(acc + 8, a1, d0);
    }

    const float4* b4 = reinterpret_cast<const float4*>(b);
    float4* o4 = reinterpret_cast<float4*>(&out[(size_t)node * EMBED_DIM]);
    #pragma unroll
    for (int p = 0; p < 2; p++) {
        int u = p * 32 + lane;
        #pragma unroll
        for (int q = 0; q < 2; q++) {
            float4 bb = __ldg(&b4[u * 2 + q]);
            float4 v;
            float t;
            t = acc[p * 8 + q * 4 + 0] * sc + bb.x; v.x = (t >= 0.f) ? t : NEG_SLOPE * t;
            t = acc[p * 8 + q * 4 + 1] * sc + bb.y; v.y = (t >= 0.f) ? t : NEG_SLOPE * t;
            t = acc[p * 8 + q * 4 + 2] * sc + bb.z; v.z = (t >= 0.f) ? t : NEG_SLOPE * t;
            t = acc[p * 8 + q * 4 + 3] * sc + bb.w; v.w = (t >= 0.f) ? t : NEG_SLOPE * t;
            o4[u * 2 + q] = v;
        }
    }
}

// -------------------- launch --------------------
extern "C" void kernel_launch(void* const* d_in, const int* in_sizes, int n_in,
                              void* d_out, int out_size) {
    const float* X = (const float*)d_in[0];
    const float* W = (const float*)d_in[1];
    const float* b = (const float*)d_in[2];
    const int* edge = (const int*)d_in[3];
    const int* src = edge;
    const int* dst = edge + N_EDGES;
    float* out = (float*)d_out;

    // one-time host-side resources (no device memory involved)
    static cudaStream_t s1 = nullptr;
    static cudaEvent_t evFork = nullptr, evJoin = nullptr;
    if (s1 == nullptr) {
        cudaStreamCreateWithFlags(&s1, cudaStreamNonBlocking);
        cudaEventCreateWithFlags(&evFork, cudaEventDisableTiming);
        cudaEventCreateWithFlags(&evJoin, cudaEventDisableTiming);
    }

    // fork: CSR/degree chain on s1, GEMM path on the main stream
    cudaEventRecord(evFork, 0);
    cudaStreamWaitEvent(s1, evFork, 0);

    init_deg_kernel<<<(N_NODES + 255) / 256, 256, 0, s1>>>();
    count_deg_kernel<<<(N_EDGES + 255) / 256, 256, 0, s1>>>(dst);
    scan_passA<<<SCAN_BLOCKS, 256, 0, s1>>>();
    scan_passB<<<1, 256, 0, s1>>>();
    scan_passC<<<SCAN_BLOCKS, 256, 0, s1>>>();
    csr_fill_kernel<<<(N_EDGES + 255) / 256, 256, 0, s1>>>(src, dst);
    cudaEventRecord(evJoin, s1);

    size_t cx_threads = (size_t)N_NODES * EMBED_DIM / 8;
    convert_x_kernel<<<(unsigned)((cx_threads + 255) / 256), 256>>>(X);
    convert_w_kernel<<<dim3(16, 16), dim3(32, 8)>>>(W);

    cudaFuncSetAttribute(gemm_mma_kernel,
                         cudaFuncAttributeMaxDynamicSharedMemorySize, SMEM_TOTAL);
    dim3 ggrid(EMBED_DIM / BN, (N_NODES + BM - 1) / BM);
    gemm_mma_kernel<<<ggrid, 256, SMEM_TOTAL>>>();

    // join: gather needs CSR + dinv + H
    cudaStreamWaitEvent(0, evJoin, 0);
    gather_kernel<<<(N_NODES + 7) / 8, 256>>>(b, out);
}